// round 14
// baseline (speedup 1.0000x reference)
#include <cuda_runtime.h>
#include <cuda_fp16.h>
#include <math.h>
#include <stdint.h>

typedef unsigned long long ull;
typedef long long ll;

#define TT    2048
#define NH    32
#define NKV   8
#define HD    128
#define NSALT 512
#define NSEG  4
#define SMAXK 512
#define SCALE_L2E 0.12751742788f   /* (1/sqrt(128)) * log2(e), folded into Q */

#define CVT_BLKS 2048
#define VN_BLKS  512
#define VD_BLKS  128

// k_qk smem (96KB): Q[0,16K) KB0[16K,48K) KB1[48K,80K) Pst[80K,96K)
#define QOFF 0u
#define KB0  16384u
#define KB1  49152u
#define PSTO 81920u
// k_pv smem (96KB): A0[0,16K) B0[16K,48K) A1[48K,64K) B1[64K,96K)
#define PV_A0 0u
#define PV_B0 16384u
#define PV_A1 49152u
#define PV_B1 65536u

// ---------------- scratch (device globals: allocation-free) ----------------
__device__ float g_inv[(size_t)TT * NH];
__device__ float g_cp[(size_t)TT * NKV * 3];   // per-(query, kv-group) partial ab/aa/bb
__device__ __half g_k[(size_t)TT * NKV * HD];
__device__ __half g_Posal[(size_t)NSALT * NH * SMAXK];
__device__ __half g_vnT[(size_t)NKV * HD * TT];
__device__ __half g_vdT[(size_t)NKV * HD * NSALT];
__device__ int   g_idx[NSALT];
__device__ int   g_cu[NSEG + 1];
__device__ int   g_salpos[TT];
__device__ int   g_salst[NSEG];
__device__ int   g_salcnt[NSEG];

// ---------------- helpers ----------------
__device__ __forceinline__ uint32_t smem_to_u32(const void* p) {
    uint32_t a;
    asm("{ .reg .u64 t; cvta.to.shared.u64 t, %1; cvt.u32.u64 %0, t; }" : "=r"(a) : "l"(p));
    return a;
}
__device__ __forceinline__ void ldsm4(uint32_t* r, uint32_t addr) {
    asm volatile("ldmatrix.sync.aligned.m8n8.x4.shared.b16 {%0,%1,%2,%3}, [%4];"
        : "=r"(r[0]), "=r"(r[1]), "=r"(r[2]), "=r"(r[3]) : "r"(addr));
}
__device__ __forceinline__ void mma16816(float* c, const uint32_t* a, uint32_t b0, uint32_t b1) {
    asm volatile("mma.sync.aligned.m16n8k16.row.col.f32.f16.f16.f32 "
        "{%0,%1,%2,%3}, {%4,%5,%6,%7}, {%8,%9}, {%0,%1,%2,%3};"
        : "+f"(c[0]), "+f"(c[1]), "+f"(c[2]), "+f"(c[3])
        : "r"(a[0]), "r"(a[1]), "r"(a[2]), "r"(a[3]), "r"(b0), "r"(b1));
}
__device__ __forceinline__ void cpa16(uint32_t dst, const void* src, bool valid) {
    int sz = valid ? 16 : 0;
    asm volatile("cp.async.cg.shared.global [%0], [%1], 16, %2;"
        :: "r"(dst), "l"(src), "r"(sz) : "memory");
}
#define CP_COMMIT() asm volatile("cp.async.commit_group;" ::: "memory")
#define CP_WAIT0()  asm volatile("cp.async.wait_group 0;" ::: "memory")
#define CP_WAIT1()  asm volatile("cp.async.wait_group 1;" ::: "memory")

__device__ __forceinline__ float fexp2(float x) {
    float r;
    asm("ex2.approx.f32 %0, %1;" : "=f"(r) : "f"(x));
    return r;
}

// 64(m)x128(n)x128(k) 1-pass fp16 HMMA. A single plane @aOff; B single plane @bOff.
// Rows 256B, 16B-chunk XOR swizzle. 8 warps = 2(m) x 4(n). acc[2][4][4].
__device__ __forceinline__ void hmma_1p(uint32_t sb, uint32_t aOff, uint32_t bOff,
                                        float acc[2][4][4], int wid, int lane) {
    const int wm = wid >> 2, wn = wid & 3;
    uint32_t a_ad[2], a_rx[2];
#pragma unroll
    for (int mf = 0; mf < 2; mf++) {
        int row = wm * 32 + mf * 16 + (lane & 15);
        a_ad[mf] = sb + aOff + row * 256;
        a_rx[mf] = ((uint32_t)(row & 7)) << 4;
    }
    const int achunk = (lane >> 4);
    uint32_t b_ad[2], b_rx[2];
#pragma unroll
    for (int bg = 0; bg < 2; bg++) {
        int n = wn * 32 + bg * 16 + (lane & 7) + ((lane >> 4) << 3);
        b_ad[bg] = sb + bOff + n * 256;
        b_rx[bg] = ((uint32_t)(n & 7)) << 4;
    }
    const int bchunk = (lane >> 3) & 1;
#pragma unroll
    for (int ks = 0; ks < 8; ks++) {
        uint32_t ah[2][4];
#pragma unroll
        for (int mf = 0; mf < 2; mf++) {
            uint32_t coff = (((uint32_t)(ks * 2 + achunk)) << 4) ^ a_rx[mf];
            ldsm4(ah[mf], a_ad[mf] + coff);
        }
        uint32_t bh[2][4];
#pragma unroll
        for (int bg = 0; bg < 2; bg++) {
            uint32_t coff = (((uint32_t)(ks * 2 + bchunk)) << 4) ^ b_rx[bg];
            ldsm4(bh[bg], b_ad[bg] + coff);
        }
#pragma unroll
        for (int mf = 0; mf < 2; mf++)
#pragma unroll
            for (int nf = 0; nf < 4; nf++) {
                int bg = nf >> 1, sel = (nf & 1) * 2;
                mma16816(acc[mf][nf], ah[mf], bh[bg][sel], bh[bg][sel + 1]);
            }
    }
}

// store one P value into swizzled Pstage (single fp16 plane @PSTO)
__device__ __forceinline__ void sts_p(char* dsm, int row, int salcol, float val) {
    uint32_t off = (uint32_t)row * 256 + ((((uint32_t)(salcol >> 3)) ^ (uint32_t)(row & 7)) << 4)
                 + (uint32_t)((2 * salcol) & 15);
    *(__half*)(dsm + PSTO + off) = __float2half_rn(val);
}

// ---------------- K0a: decode indices, segment tables ----------------
__global__ void k_prep(const void* idx_raw, const void* cu_raw) {
    const int* i32 = (const int*)idx_raw;
    const int* c32 = (const int*)cu_raw;
    const bool idx64 = (i32[1] == 0);
    const bool cu64  = (c32[1] == 0);
    const int t = threadIdx.x;

    for (int i = t; i < NSALT; i += 256)
        g_idx[i] = idx64 ? (int)((const long long*)idx_raw)[i] : i32[i];
    if (t <= NSEG)
        g_cu[t] = cu64 ? (int)((const long long*)cu_raw)[t] : c32[t];
    for (int i = t; i < TT; i += 256) g_salpos[i] = -1;
    __syncthreads();
    for (int i = t; i < NSALT; i += 256) g_salpos[g_idx[i]] = i;
    if (t == 0) {
        for (int s = 0; s < NSEG; s++) {
            int a = 0;
            while (a < NSALT && g_idx[a] < g_cu[s]) a++;
            int b = a;
            while (b < NSALT && g_idx[b] < g_cu[s + 1]) b++;
            g_salst[s] = a;
            g_salcnt[s] = b - a;
        }
    }
}

// ---------------- K0b (merged): K cvt || build_vn || build_vd (single fp16) ----------------
__global__ void __launch_bounds__(256) k_pre(const float* __restrict__ kk,
                                             const float* __restrict__ v, const float* __restrict__ vc) {
    extern __shared__ float tile[];   // [32][129]
    const int bx = blockIdx.x;
    const int tid = threadIdx.x;

    if (bx < CVT_BLKS) {
        int i = bx * 256 + tid;
        float4 x = ((const float4*)kk)[i];
        __half2 h2[2];
        h2[0] = __floats2half2_rn(x.x, x.y);
        h2[1] = __floats2half2_rn(x.z, x.w);
        *(uint2*)(g_k + 4 * (size_t)i) = *(uint2*)h2;
        return;
    }

    if (bx < CVT_BLKS + VN_BLKS) {
        int t2 = bx - CVT_BLKS;
        int kc = t2 >> 3, g = t2 & 7;
#pragma unroll
        for (int it = 0; it < 4; it++) {
            int fi = tid + it * 256;
            int key = fi >> 5, c4 = fi & 31;
            int gk = kc * 32 + key;
            int sp = g_salpos[gk];
            const float* src = (sp >= 0) ? v + ((size_t)sp * NKV + g) * HD + c4 * 4
                                         : vc + ((size_t)gk * NKV + g) * HD + c4 * 4;
            float4 x = *(const float4*)src;
            float* tr = tile + key * 129 + c4 * 4;
            tr[0] = x.x; tr[1] = x.y; tr[2] = x.z; tr[3] = x.w;
        }
        __syncthreads();
#pragma unroll
        for (int it = 0; it < 8; it++) {
            int wi = tid + it * 256;
            int d = wi >> 4, kp = wi & 15;
            float v0 = tile[(2 * kp) * 129 + d], v1 = tile[(2 * kp + 1) * 129 + d];
            size_t dst = ((size_t)g * HD + d) * TT + kc * 32 + 2 * kp;
            *(__half2*)(g_vnT + dst) = __floats2half2_rn(v0, v1);
        }
        return;
    }

    {
        int t2 = bx - CVT_BLKS - VN_BLKS;
        int kc = t2 >> 3, g = t2 & 7;
#pragma unroll
        for (int it = 0; it < 4; it++) {
            int fi = tid + it * 256;
            int sidx = fi >> 5, c4 = fi & 31;
            int sal = kc * 32 + sidx;
            const float* pv = v  + ((size_t)sal * NKV + g) * HD + c4 * 4;
            const float* pc = vc + ((size_t)g_idx[sal] * NKV + g) * HD + c4 * 4;
            float4 a = *(const float4*)pv;
            float4 b = *(const float4*)pc;
            float* tr = tile + sidx * 129 + c4 * 4;
            tr[0] = a.x - b.x; tr[1] = a.y - b.y; tr[2] = a.z - b.z; tr[3] = a.w - b.w;
        }
        __syncthreads();
#pragma unroll
        for (int it = 0; it < 8; it++) {
            int wi = tid + it * 256;
            int d = wi >> 4, kp = wi & 15;
            float v0 = tile[(2 * kp) * 129 + d], v1 = tile[(2 * kp + 1) * 129 + d];
            size_t dst = ((size_t)g * HD + d) * NSALT + kc * 32 + 2 * kp;
            *(__half2*)(g_vdT + dst) = __floats2half2_rn(v0, v1);
        }
    }
}

// ---------------- K1: fused QK^T + exp + rowsum + delta-PV + cos partials ----------------
__device__ __forceinline__ void qk_loadK(uint32_t sb, uint32_t buf, int tid, int nt, int s0, int L, int g) {
#pragma unroll
    for (int it = 0; it < 8; it++) {
        int idx = tid + it * 256;
        int r = idx >> 4, ch = idx & 15;
        uint32_t d = (uint32_t)(r * 256) + (((uint32_t)(ch ^ (r & 7))) << 4);
        int jg = nt * 128 + r;
        bool v = jg < L;
        size_t o = v ? (((size_t)(s0 + jg) * NKV + g) * HD + ch * 8) : 0;
        cpa16(sb + buf + d, g_k + o, v);
    }
}

__global__ void __launch_bounds__(256, 2) k_qk(const float* __restrict__ qf,
                                               const float* __restrict__ cc, float* __restrict__ outc) {
    extern __shared__ char dsm[];
    __shared__ int s_sp[SMAXK];
    __shared__ float s_red[64 * 4];
    __shared__ float s_cp[64 * 12];   // [row][wn][3]
    const int sg = blockIdx.y;
    const int s = sg >> 3, g = sg & 7;
    const int s0 = g_cu[s];
    const int L = g_cu[s + 1] - s0;
    const int mBase = blockIdx.x * 64;
    if (mBase >= 4 * L) return;
    const int salst = g_salst[s], salcnt = g_salcnt[s];

    const int tid = threadIdx.x, wid = tid >> 5, lane = tid & 31;
    const int wm = wid >> 2, wn = wid & 3;
    const uint32_t sb = smem_to_u32(dsm);

    qk_loadK(sb, KB0, tid, 0, s0, L, g);
    CP_COMMIT();
    qk_loadK(sb, KB1, tid, 1, s0, L, g);
    CP_COMMIT();

    for (int j = tid; j < L; j += 256) {
        int sp = g_salpos[s0 + j];
        s_sp[j] = sp >= 0 ? sp - salst : -1;
    }

    // zero Pstage (16KB)
    {
        uint4 z = make_uint4(0, 0, 0, 0);
#pragma unroll
        for (int it = 0; it < 4; it++)
            *(uint4*)(dsm + PSTO + (size_t)(tid + it * 256) * 16) = z;
    }

    // Q tile: fp32 -> fp16(q*SCALE_L2E) single plane, swizzled STS
#pragma unroll
    for (int it = 0; it < 4; it++) {
        int idx = tid + it * 256;
        int r = idx >> 4, ch = idx & 15;
        uint32_t d = (uint32_t)(r * 256) + (((uint32_t)(ch ^ (r & 7))) << 4);
        int mm = mBase + r, il = mm >> 2, hh = mm & 3;
        __half2 h2[4];
        if (il < L) {
            const float4* src = (const float4*)(qf + ((size_t)(s0 + il) * NH + 4 * g + hh) * HD + ch * 8);
            float4 x0 = src[0], x1 = src[1];
            h2[0] = __floats2half2_rn(x0.x * SCALE_L2E, x0.y * SCALE_L2E);
            h2[1] = __floats2half2_rn(x0.z * SCALE_L2E, x0.w * SCALE_L2E);
            h2[2] = __floats2half2_rn(x1.x * SCALE_L2E, x1.y * SCALE_L2E);
            h2[3] = __floats2half2_rn(x1.z * SCALE_L2E, x1.w * SCALE_L2E);
        } else {
            h2[0] = h2[1] = h2[2] = h2[3] = __floats2half2_rn(0.f, 0.f);
        }
        *(uint4*)(dsm + d) = *(uint4*)h2;
    }

    // per-row metadata (Posal base for salient rows)
    ll pb0[2], pb1[2];
    bool ok0[2], ok1[2];
    int rb[2];
#pragma unroll
    for (int mf = 0; mf < 2; mf++) {
        rb[mf] = wm * 32 + mf * 16 + (lane >> 2);
        int mr0 = mBase + rb[mf];
        int mr1 = mr0 + 8;
        int il0 = mr0 >> 2, h0 = mr0 & 3;
        int il1 = mr1 >> 2, h1 = mr1 & 3;
        ok0[mf] = il0 < L; ok1[mf] = il1 < L;
        int sp0 = ok0[mf] ? g_salpos[s0 + il0] : -1;
        int sp1 = ok1[mf] ? g_salpos[s0 + il1] : -1;
        pb0[mf] = sp0 >= 0 ? ((ll)sp0 * NH + 4 * g + h0) * SMAXK : -1;
        pb1[mf] = sp1 >= 0 ? ((ll)sp1 * NH + 4 * g + h1) * SMAXK : -1;
    }

    float rs0[2] = {0.f, 0.f}, rs1[2] = {0.f, 0.f};

    for (int nt = 0; nt < 4; nt++) {
        CP_WAIT1();
        __syncthreads();

        float acc[2][4][4];
#pragma unroll
        for (int a = 0; a < 2; a++)
#pragma unroll
            for (int b = 0; b < 4; b++)
#pragma unroll
                for (int c = 0; c < 4; c++) acc[a][b][c] = 0.f;

        uint32_t buf = (nt & 1) ? KB1 : KB0;
        hmma_1p(sb, QOFF, buf, acc, wid, lane);
        __syncthreads();
        if (nt < 2) {
            qk_loadK(sb, buf, tid, nt + 2, s0, L, g);
            CP_COMMIT();
        } else if (nt == 2) {
#pragma unroll
            for (int it = 0; it < 8; it++) {
                int idx = tid + it * 256;
                int r = idx >> 4, ch = idx & 15;
                uint32_t d = (uint32_t)(r * 256) + (((uint32_t)(ch ^ (r & 7))) << 4);
                bool vb = (ch * 8 < salcnt);
                size_t ib = vb ? (((size_t)(g * HD + r)) * NSALT + salst + ch * 8) : 0;
                cpa16(sb + KB0 + d, g_vdT + ib, vb);
            }
            CP_COMMIT();
        }

#pragma unroll
        for (int nf = 0; nf < 4; nf++) {
            int col = nt * 128 + wn * 32 + nf * 8 + (lane & 3) * 2;
            bool c0 = col < L, c1 = col + 1 < L;
            int spa = c0 ? s_sp[col] : -1;
            int spb = c1 ? s_sp[col + 1] : -1;
#pragma unroll
            for (int mf = 0; mf < 2; mf++) {
                float* c = acc[mf][nf];
                float e0 = (ok0[mf] && c0) ? fexp2(c[0]) : 0.f;
                float e1 = (ok0[mf] && c1) ? fexp2(c[1]) : 0.f;
                float e2 = (ok1[mf] && c0) ? fexp2(c[2]) : 0.f;
                float e3 = (ok1[mf] && c1) ? fexp2(c[3]) : 0.f;
                rs0[mf] += e0 + e1;
                rs1[mf] += e2 + e3;
                int r0 = rb[mf], r1 = r0 + 8;
                if (spa >= 0) {
                    if (ok0[mf]) sts_p(dsm, r0, spa, e0);
                    if (ok1[mf]) sts_p(dsm, r1, spa, e2);
                }
                if (spb >= 0) {
                    if (ok0[mf]) sts_p(dsm, r0, spb, e1);
                    if (ok1[mf]) sts_p(dsm, r1, spb, e3);
                }
                if (pb0[mf] >= 0 && c0)
                    *(__half2*)(g_Posal + pb0[mf] + col) = __floats2half2_rn(e0, e1);
                if (pb1[mf] >= 0 && c0)
                    *(__half2*)(g_Posal + pb1[mf] + col) = __floats2half2_rn(e2, e3);
            }
        }
    }

    // rowsum reduction across n-warps
#pragma unroll
    for (int mf = 0; mf < 2; mf++) {
        rs0[mf] += __shfl_xor_sync(0xffffffffu, rs0[mf], 1);
        rs0[mf] += __shfl_xor_sync(0xffffffffu, rs0[mf], 2);
        rs1[mf] += __shfl_xor_sync(0xffffffffu, rs1[mf], 1);
        rs1[mf] += __shfl_xor_sync(0xffffffffu, rs1[mf], 2);
    }
    if ((lane & 3) == 0) {
#pragma unroll
        for (int mf = 0; mf < 2; mf++) {
            s_red[rb[mf] * 4 + wn] = rs0[mf];
            s_red[(rb[mf] + 8) * 4 + wn] = rs1[mf];
        }
    }
    CP_WAIT0();           // vdT in
    __syncthreads();

    // g_inv for osal
    if (tid < 64) {
        int mm = mBase + tid, il = mm >> 2, h = mm & 3;
        if (il < L) {
            float s4 = s_red[tid * 4] + s_red[tid * 4 + 1] + s_red[tid * 4 + 2] + s_red[tid * 4 + 3];
            g_inv[(size_t)(s0 + il) * NH + 4 * g + h] = 1.f / s4;
        }
    }

    // delta PV: Pstage (A) @ vdT (B @KB0), 1-pass
    float pv[2][4][4];
#pragma unroll
    for (int a = 0; a < 2; a++)
#pragma unroll
        for (int b = 0; b < 4; b++)
#pragma unroll
            for (int c = 0; c < 4; c++) pv[a][b][c] = 0.f;
    hmma_1p(sb, PSTO, KB0, pv, wid, lane);

    // output (non-salient rows) + cos partials
    float cp[4][3];
#pragma unroll
    for (int sl = 0; sl < 4; sl++) cp[sl][0] = cp[sl][1] = cp[sl][2] = 0.f;

#pragma unroll
    for (int mf = 0; mf < 2; mf++) {
        int r0 = rb[mf], r1 = r0 + 8;
        int mr0 = mBase + r0, mr1 = mBase + r1;
        int il0 = mr0 >> 2, h0 = mr0 & 3;
        int il1 = mr1 >> 2, h1 = mr1 & 3;
        bool w0 = (il0 < L) && (g_salpos[s0 + il0] < 0);
        bool w1 = (il1 < L) && (g_salpos[s0 + il1] < 0);
        float inv0 = 0.f, inv1 = 0.f;
        if (w0) inv0 = 1.f / (s_red[r0 * 4] + s_red[r0 * 4 + 1] + s_red[r0 * 4 + 2] + s_red[r0 * 4 + 3]);
        if (w1) inv1 = 1.f / (s_red[r1 * 4] + s_red[r1 * 4 + 1] + s_red[r1 * 4 + 2] + s_red[r1 * 4 + 3]);
        size_t id0 = (size_t)(s0 + il0) * NH + 4 * g + h0;
        size_t id1 = (size_t)(s0 + il1) * NH + 4 * g + h1;
#pragma unroll
        for (int nf = 0; nf < 4; nf++) {
            int dcol = wn * 32 + nf * 8 + (lane & 3) * 2;
            float* c = pv[mf][nf];
            if (w0) {
                size_t ob = id0 * HD + dcol;
                float2 cv = *(const float2*)(cc + ob);
                float ox = cv.x + inv0 * c[0], oy = cv.y + inv0 * c[1];
                *(float2*)(outc + ob) = make_float2(ox, oy);
                cp[mf * 2][0] += cv.x * ox + cv.y * oy;
                cp[mf * 2][1] += cv.x * cv.x + cv.y * cv.y;
                cp[mf * 2][2] += ox * ox + oy * oy;
            }
            if (w1) {
                size_t ob = id1 * HD + dcol;
                float2 cv = *(const float2*)(cc + ob);
                float ox = cv.x + inv1 * c[2], oy = cv.y + inv1 * c[3];
                *(float2*)(outc + ob) = make_float2(ox, oy);
                cp[mf * 2 + 1][0] += cv.x * ox + cv.y * oy;
                cp[mf * 2 + 1][1] += cv.x * cv.x + cv.y * cv.y;
                cp[mf * 2 + 1][2] += ox * ox + oy * oy;
            }
        }
    }

    // cos partial reduction: over 4 column-lanes, then smem over wn + 4 head-rows
#pragma unroll
    for (int sl = 0; sl < 4; sl++)
#pragma unroll
        for (int c = 0; c < 3; c++) {
            cp[sl][c] += __shfl_xor_sync(0xffffffffu, cp[sl][c], 1);
            cp[sl][c] += __shfl_xor_sync(0xffffffffu, cp[sl][c], 2);
        }
    if ((lane & 3) == 0) {
#pragma unroll
        for (int mf = 0; mf < 2; mf++) {
            int r0 = rb[mf];
#pragma unroll
            for (int c = 0; c < 3; c++) {
                s_cp[r0 * 12 + wn * 3 + c] = cp[mf * 2][c];
                s_cp[(r0 + 8) * 12 + wn * 3 + c] = cp[mf * 2 + 1][c];
            }
        }
    }
    __syncthreads();
    if (tid < 16) {
        int il = (mBase >> 2) + tid;
        if (il < L) {
            float A = 0.f, B = 0.f, C = 0.f;
#pragma unroll
            for (int r = 0; r < 4; r++)
#pragma unroll
                for (int w = 0; w < 4; w++) {
                    int base = (tid * 4 + r) * 12 + w * 3;
                    A += s_cp[base]; B += s_cp[base + 1]; C += s_cp[base + 2];
                }
            size_t slot = ((size_t)(s0 + il) * NKV + g) * 3;
            g_cp[slot] = A; g_cp[slot + 1] = B; g_cp[slot + 2] = C;
        }
    }
}

// ---------------- K2: osal: salient rows out = inv * (Posal @ vnT) + cos partials ----------------
__global__ void __launch_bounds__(256, 2) k_pv(const float* __restrict__ cc, float* __restrict__ outc) {
    extern __shared__ char dsm[];
    __shared__ float s_cp[64 * 12];
    const int sg = blockIdx.y;
    const int s = sg >> 3, g = sg & 7;
    const int s0 = g_cu[s];
    const int L = g_cu[s + 1] - s0;
    const int salst = g_salst[s], salcnt = g_salcnt[s];

    const int tid = threadIdx.x, wid = tid >> 5, lane = tid & 31;
    const int wm = wid >> 2, wn = wid & 3;
    const uint32_t sb = smem_to_u32(dsm);

    const int mBase = blockIdx.x * 64;
    if (mBase >= 4 * salcnt) return;

    auto loadA = [&](uint32_t buf, int kc) {
#pragma unroll
        for (int it = 0; it < 4; it++) {
            int idx = tid + it * 256;
            int r = idx >> 4, ch = idx & 15;
            uint32_t d = (uint32_t)(r * 256) + (((uint32_t)(ch ^ (r & 7))) << 4);
            int m = mBase + r, saloc = m >> 2, hh = m & 3;
            int kk = kc * 128 + ch * 8;
            bool va = (saloc < salcnt) && (kk < L);
            size_t ia = va ? (((size_t)(salst + saloc) * NH + 4 * g + hh) * SMAXK + kk) : 0;
            cpa16(sb + buf + d, g_Posal + ia, va);
        }
    };
    auto loadB = [&](uint32_t buf, int kc) {
#pragma unroll
        for (int it = 0; it < 8; it++) {
            int idx = tid + it * 256;
            int r = idx >> 4, ch = idx & 15;
            uint32_t d = (uint32_t)(r * 256) + (((uint32_t)(ch ^ (r & 7))) << 4);
            int kk = kc * 128 + ch * 8;
            bool vb = (kk < L);
            size_t ib = vb ? (((size_t)(g * HD + r)) * TT + s0 + kk) : 0;
            cpa16(sb + buf + d, g_vnT + ib, vb);
        }
    };

    const int nkc = (L + 127) / 128;
    loadA(PV_A0, 0); loadB(PV_B0, 0);
    CP_COMMIT();
    if (nkc > 1) { loadA(PV_A1, 1); loadB(PV_B1, 1); }
    CP_COMMIT();

    float acc[2][4][4];
#pragma unroll
    for (int a = 0; a < 2; a++)
#pragma unroll
        for (int b = 0; b < 4; b++)
#pragma unroll
            for (int c = 0; c < 4; c++) acc[a][b][c] = 0.f;

    for (int kc = 0; kc < nkc; kc++) {
        if (kc == nkc - 1) { CP_WAIT0(); } else { CP_WAIT1(); }
        __syncthreads();
        uint32_t aB = (kc & 1) ? PV_A1 : PV_A0;
        uint32_t bB = (kc & 1) ? PV_B1 : PV_B0;
        hmma_1p(sb, aB, bB, acc, wid, lane);
        __syncthreads();
        if (kc + 2 < nkc) {
            loadA(aB, kc + 2); loadB(bB, kc + 2);
            CP_COMMIT();
        }
    }

    float cp[4][3];
#pragma unroll
    for (int sl = 0; sl < 4; sl++) cp[sl][0] = cp[sl][1] = cp[sl][2] = 0.f;
    int rbv[2];

#pragma unroll
    for (int mf = 0; mf < 2; mf++) {
        int r0 = wm * 32 + mf * 16 + (lane >> 2);
        rbv[mf] = r0;
        int mr0 = mBase + r0;
        int mr1 = mr0 + 8;
        int sa0 = mr0 >> 2, h0 = mr0 & 3;
        int sa1 = mr1 >> 2, h1 = mr1 & 3;
        bool ok0 = sa0 < salcnt, ok1 = sa1 < salcnt;
        size_t id0 = 0, id1 = 0;
        float inv0 = 0.f, inv1 = 0.f;
        if (ok0) { id0 = (size_t)g_idx[salst + sa0] * NH + 4 * g + h0; inv0 = g_inv[id0]; }
        if (ok1) { id1 = (size_t)g_idx[salst + sa1] * NH + 4 * g + h1; inv1 = g_inv[id1]; }
#pragma unroll
        for (int nf = 0; nf < 4; nf++) {
            int dcol = wn * 32 + nf * 8 + (lane & 3) * 2;
            float* c = acc[mf][nf];
            if (ok0) {
                size_t ob = id0 * HD + dcol;
                float2 cv = *(const float2*)(cc + ob);
                float ox = inv0 * c[0], oy = inv0 * c[1];
                *(float2*)(outc + ob) = make_float2(ox, oy);
                cp[mf * 2][0] += cv.x * ox + cv.y * oy;
                cp[mf * 2][1] += cv.x * cv.x + cv.y * cv.y;
                cp[mf * 2][2] += ox * ox + oy * oy;
            }
            if (ok1) {
                size_t ob = id1 * HD + dcol;
                float2 cv = *(const float2*)(cc + ob);
                float ox = inv1 * c[2], oy = inv1 * c[3];
                *(float2*)(outc + ob) = make_float2(ox, oy);
                cp[mf * 2 + 1][0] += cv.x * ox + cv.y * oy;
                cp[mf * 2 + 1][1] += cv.x * cv.x + cv.y * cv.y;
                cp[mf * 2 + 1][2] += ox * ox + oy * oy;
            }
        }
    }

#pragma unroll
    for (int sl = 0; sl < 4; sl++)
#pragma unroll
        for (int c = 0; c < 3; c++) {
            cp[sl][c] += __shfl_xor_sync(0xffffffffu, cp[sl][c], 1);
            cp[sl][c] += __shfl_xor_sync(0xffffffffu, cp[sl][c], 2);
        }
    if ((lane & 3) == 0) {
#pragma unroll
        for (int mf = 0; mf < 2; mf++) {
            int r0 = rbv[mf];
#pragma unroll
            for (int c = 0; c < 3; c++) {
                s_cp[r0 * 12 + wn * 3 + c] = cp[mf * 2][c];
                s_cp[(r0 + 8) * 12 + wn * 3 + c] = cp[mf * 2 + 1][c];
            }
        }
    }
    __syncthreads();
    if (tid < 16) {
        int saloc = (mBase >> 2) + tid;
        if (saloc < salcnt) {
            float A = 0.f, B = 0.f, C = 0.f;
#pragma unroll
            for (int r = 0; r < 4; r++)
#pragma unroll
                for (int w = 0; w < 4; w++) {
                    int base = (tid * 4 + r) * 12 + w * 3;
                    A += s_cp[base]; B += s_cp[base + 1]; C += s_cp[base + 2];
                }
            size_t slot = ((size_t)g_idx[salst + saloc] * NKV + g) * 3;
            g_cp[slot] = A; g_cp[slot + 1] = B; g_cp[slot + 2] = C;
        }
    }
}

// ---------------- K3: finish cosine from partials ----------------
__global__ void __launch_bounds__(256) k_cosf(float* __restrict__ cosv) {
    int i = blockIdx.x * 256 + threadIdx.x;
    float ab = 0.f, aa = 0.f, bb = 0.f;
#pragma unroll
    for (int g = 0; g < NKV; g++) {
        size_t slot = ((size_t)i * NKV + g) * 3;
        ab += g_cp[slot]; aa += g_cp[slot + 1]; bb += g_cp[slot + 2];
    }
    cosv[i] = ab / (sqrtf(aa) * sqrtf(bb) + 1e-8f);
}

// ---------------- launch ----------------
extern "C" void kernel_launch(void* const* d_in, const int* in_sizes, int n_in,
                              void* d_out, int out_size) {
    const float* q       = (const float*)d_in[0];
    const float* k       = (const float*)d_in[1];
    const float* v       = (const float*)d_in[2];
    const float* v_cache = (const float*)d_in[3];
    const float* c_cache = (const float*)d_in[4];
    const void*  idx     = d_in[5];
    const void*  cu      = d_in[6];

    float* outc = (float*)d_out;
    float* cosv = outc + (size_t)(out_size - TT);

    cudaFuncSetAttribute(k_qk,  cudaFuncAttributeMaxDynamicSharedMemorySize, 98304);
    cudaFuncSetAttribute(k_pv,  cudaFuncAttributeMaxDynamicSharedMemorySize, 98304);
    cudaFuncSetAttribute(k_pre, cudaFuncAttributeMaxDynamicSharedMemorySize, 16512);

    k_prep<<<1, 256>>>(idx, cu);
    k_pre<<<CVT_BLKS + VN_BLKS + VD_BLKS, 256, 16512>>>(k, v, v_cache);
    k_qk<<<dim3(32, 32), 256, 98304>>>(q, c_cache, outc);
    k_pv<<<dim3(8, 32), 256, 98304>>>(c_cache, outc);
    k_cosf<<<TT / 256, 256>>>(cosv);
}

// round 15
// speedup vs baseline: 1.0495x; 1.0495x over previous
#include <cuda_runtime.h>
#include <cuda_fp16.h>
#include <math.h>
#include <stdint.h>

typedef unsigned long long ull;
typedef long long ll;

#define TT    2048
#define NH    32
#define NKV   8
#define HD    128
#define NSALT 512
#define NSEG  4
#define SMAXK 512
#define SCALE_L2E 0.12751742788f   /* (1/sqrt(128)) * log2(e), folded into Q */

#define CVT_BLKS 2048
#define VN_BLKS  512
#define VD_BLKS  128

// k_qk smem (96KB): Q[0,16K) KB0[16K,48K) KB1[48K,80K) Pst[80K,96K)
#define QOFF 0u
#define KB0  16384u
#define KB1  49152u
#define PSTO 81920u
// k_pv smem (64KB): A0[0,16K) A1[16K,32K) B0[32K,48K) B1[48K,64K)
#define PV_A0 0u
#define PV_A1 16384u
#define PV_B0 32768u
#define PV_B1 49152u

// ---------------- scratch (device globals: allocation-free) ----------------
__device__ float g_inv[(size_t)TT * NH];
__device__ __half g_k[(size_t)TT * NKV * HD];
__device__ __half g_Posal[(size_t)NSALT * NH * SMAXK];
__device__ __half g_vnT[(size_t)NKV * HD * TT];
__device__ __half g_vdT[(size_t)NKV * HD * NSALT];
__device__ int   g_idx[NSALT];
__device__ int   g_cu[NSEG + 1];
__device__ int   g_salpos[TT];
__device__ int   g_salst[NSEG];
__device__ int   g_salcnt[NSEG];

// ---------------- helpers ----------------
__device__ __forceinline__ uint32_t smem_to_u32(const void* p) {
    uint32_t a;
    asm("{ .reg .u64 t; cvta.to.shared.u64 t, %1; cvt.u32.u64 %0, t; }" : "=r"(a) : "l"(p));
    return a;
}
__device__ __forceinline__ void ldsm4(uint32_t* r, uint32_t addr) {
    asm volatile("ldmatrix.sync.aligned.m8n8.x4.shared.b16 {%0,%1,%2,%3}, [%4];"
        : "=r"(r[0]), "=r"(r[1]), "=r"(r[2]), "=r"(r[3]) : "r"(addr));
}
__device__ __forceinline__ void mma16816(float* c, const uint32_t* a, uint32_t b0, uint32_t b1) {
    asm volatile("mma.sync.aligned.m16n8k16.row.col.f32.f16.f16.f32 "
        "{%0,%1,%2,%3}, {%4,%5,%6,%7}, {%8,%9}, {%0,%1,%2,%3};"
        : "+f"(c[0]), "+f"(c[1]), "+f"(c[2]), "+f"(c[3])
        : "r"(a[0]), "r"(a[1]), "r"(a[2]), "r"(a[3]), "r"(b0), "r"(b1));
}
__device__ __forceinline__ void cpa16(uint32_t dst, const void* src, bool valid) {
    int sz = valid ? 16 : 0;
    asm volatile("cp.async.cg.shared.global [%0], [%1], 16, %2;"
        :: "r"(dst), "l"(src), "r"(sz) : "memory");
}
#define CP_COMMIT() asm volatile("cp.async.commit_group;" ::: "memory")
#define CP_WAIT0()  asm volatile("cp.async.wait_group 0;" ::: "memory")
#define CP_WAIT1()  asm volatile("cp.async.wait_group 1;" ::: "memory")

__device__ __forceinline__ float fexp2(float x) {
    float r;
    asm("ex2.approx.f32 %0, %1;" : "=f"(r) : "f"(x));
    return r;
}

// 64(m)x128(n)x128(k) 1-pass fp16 HMMA. A single plane @aOff; B single plane @bOff.
// Rows 256B, 16B-chunk XOR swizzle. 8 warps = 2(m) x 4(n). acc[2][4][4].
__device__ __forceinline__ void hmma_1p(uint32_t sb, uint32_t aOff, uint32_t bOff,
                                        float acc[2][4][4], int wid, int lane) {
    const int wm = wid >> 2, wn = wid & 3;
    uint32_t a_ad[2], a_rx[2];
#pragma unroll
    for (int mf = 0; mf < 2; mf++) {
        int row = wm * 32 + mf * 16 + (lane & 15);
        a_ad[mf] = sb + aOff + row * 256;
        a_rx[mf] = ((uint32_t)(row & 7)) << 4;
    }
    const int achunk = (lane >> 4);
    uint32_t b_ad[2], b_rx[2];
#pragma unroll
    for (int bg = 0; bg < 2; bg++) {
        int n = wn * 32 + bg * 16 + (lane & 7) + ((lane >> 4) << 3);
        b_ad[bg] = sb + bOff + n * 256;
        b_rx[bg] = ((uint32_t)(n & 7)) << 4;
    }
    const int bchunk = (lane >> 3) & 1;
#pragma unroll
    for (int ks = 0; ks < 8; ks++) {
        uint32_t ah[2][4];
#pragma unroll
        for (int mf = 0; mf < 2; mf++) {
            uint32_t coff = (((uint32_t)(ks * 2 + achunk)) << 4) ^ a_rx[mf];
            ldsm4(ah[mf], a_ad[mf] + coff);
        }
        uint32_t bh[2][4];
#pragma unroll
        for (int bg = 0; bg < 2; bg++) {
            uint32_t coff = (((uint32_t)(ks * 2 + bchunk)) << 4) ^ b_rx[bg];
            ldsm4(bh[bg], b_ad[bg] + coff);
        }
#pragma unroll
        for (int mf = 0; mf < 2; mf++)
#pragma unroll
            for (int nf = 0; nf < 4; nf++) {
                int bg = nf >> 1, sel = (nf & 1) * 2;
                mma16816(acc[mf][nf], ah[mf], bh[bg][sel], bh[bg][sel + 1]);
            }
    }
}

// 64(m)x64(n)x128(k) 1-pass fp16 HMMA (N=64). Geometry = verified hmma_qk2 minus lo plane.
__device__ __forceinline__ void hmma_n64(uint32_t sb, uint32_t aOff, uint32_t bOff,
                                         float acc[2][2][4], int wid, int lane) {
    const int wm = wid >> 2, wn = wid & 3;
    uint32_t a_ad[2], a_rx[2];
#pragma unroll
    for (int mf = 0; mf < 2; mf++) {
        int row = wm * 32 + mf * 16 + (lane & 15);
        a_ad[mf] = sb + aOff + row * 256;
        a_rx[mf] = ((uint32_t)(row & 7)) << 4;
    }
    const int achunk = (lane >> 4);
    int n = wn * 16 + (lane & 7) + ((lane >> 4) << 3);
    uint32_t b_ad = sb + bOff + n * 256;
    uint32_t b_rx = ((uint32_t)(n & 7)) << 4;
    const int bchunk = (lane >> 3) & 1;
#pragma unroll
    for (int ks = 0; ks < 8; ks++) {
        uint32_t ah[2][4];
#pragma unroll
        for (int mf = 0; mf < 2; mf++) {
            uint32_t coff = (((uint32_t)(ks * 2 + achunk)) << 4) ^ a_rx[mf];
            ldsm4(ah[mf], a_ad[mf] + coff);
        }
        uint32_t bh[4];
        {
            uint32_t coff = (((uint32_t)(ks * 2 + bchunk)) << 4) ^ b_rx;
            ldsm4(bh, b_ad + coff);
        }
#pragma unroll
        for (int mf = 0; mf < 2; mf++)
#pragma unroll
            for (int nf = 0; nf < 2; nf++) {
                int sel = nf * 2;
                mma16816(acc[mf][nf], ah[mf], bh[sel], bh[sel + 1]);
            }
    }
}

// store one P value into swizzled Pstage (single fp16 plane @PSTO)
__device__ __forceinline__ void sts_p(char* dsm, int row, int salcol, float val) {
    uint32_t off = (uint32_t)row * 256 + ((((uint32_t)(salcol >> 3)) ^ (uint32_t)(row & 7)) << 4)
                 + (uint32_t)((2 * salcol) & 15);
    *(__half*)(dsm + PSTO + off) = __float2half_rn(val);
}

// ---------------- K0a: decode indices, segment tables ----------------
__global__ void k_prep(const void* idx_raw, const void* cu_raw) {
    const int* i32 = (const int*)idx_raw;
    const int* c32 = (const int*)cu_raw;
    const bool idx64 = (i32[1] == 0);
    const bool cu64  = (c32[1] == 0);
    const int t = threadIdx.x;

    for (int i = t; i < NSALT; i += 256)
        g_idx[i] = idx64 ? (int)((const long long*)idx_raw)[i] : i32[i];
    if (t <= NSEG)
        g_cu[t] = cu64 ? (int)((const long long*)cu_raw)[t] : c32[t];
    for (int i = t; i < TT; i += 256) g_salpos[i] = -1;
    __syncthreads();
    for (int i = t; i < NSALT; i += 256) g_salpos[g_idx[i]] = i;
    if (t == 0) {
        for (int s = 0; s < NSEG; s++) {
            int a = 0;
            while (a < NSALT && g_idx[a] < g_cu[s]) a++;
            int b = a;
            while (b < NSALT && g_idx[b] < g_cu[s + 1]) b++;
            g_salst[s] = a;
            g_salcnt[s] = b - a;
        }
    }
}

// ---------------- K0b (merged): K cvt || build_vn || build_vd (single fp16) ----------------
__global__ void __launch_bounds__(256) k_pre(const float* __restrict__ kk,
                                             const float* __restrict__ v, const float* __restrict__ vc) {
    extern __shared__ float tile[];   // [32][129]
    const int bx = blockIdx.x;
    const int tid = threadIdx.x;

    if (bx < CVT_BLKS) {
        int i = bx * 256 + tid;
        float4 x = ((const float4*)kk)[i];
        __half2 h2[2];
        h2[0] = __floats2half2_rn(x.x, x.y);
        h2[1] = __floats2half2_rn(x.z, x.w);
        *(uint2*)(g_k + 4 * (size_t)i) = *(uint2*)h2;
        return;
    }

    if (bx < CVT_BLKS + VN_BLKS) {
        int t2 = bx - CVT_BLKS;
        int kc = t2 >> 3, g = t2 & 7;
#pragma unroll
        for (int it = 0; it < 4; it++) {
            int fi = tid + it * 256;
            int key = fi >> 5, c4 = fi & 31;
            int gk = kc * 32 + key;
            int sp = g_salpos[gk];
            const float* src = (sp >= 0) ? v + ((size_t)sp * NKV + g) * HD + c4 * 4
                                         : vc + ((size_t)gk * NKV + g) * HD + c4 * 4;
            float4 x = *(const float4*)src;
            float* tr = tile + key * 129 + c4 * 4;
            tr[0] = x.x; tr[1] = x.y; tr[2] = x.z; tr[3] = x.w;
        }
        __syncthreads();
#pragma unroll
        for (int it = 0; it < 8; it++) {
            int wi = tid + it * 256;
            int d = wi >> 4, kp = wi & 15;
            float v0 = tile[(2 * kp) * 129 + d], v1 = tile[(2 * kp + 1) * 129 + d];
            size_t dst = ((size_t)g * HD + d) * TT + kc * 32 + 2 * kp;
            *(__half2*)(g_vnT + dst) = __floats2half2_rn(v0, v1);
        }
        return;
    }

    {
        int t2 = bx - CVT_BLKS - VN_BLKS;
        int kc = t2 >> 3, g = t2 & 7;
#pragma unroll
        for (int it = 0; it < 4; it++) {
            int fi = tid + it * 256;
            int sidx = fi >> 5, c4 = fi & 31;
            int sal = kc * 32 + sidx;
            const float* pv = v  + ((size_t)sal * NKV + g) * HD + c4 * 4;
            const float* pc = vc + ((size_t)g_idx[sal] * NKV + g) * HD + c4 * 4;
            float4 a = *(const float4*)pv;
            float4 b = *(const float4*)pc;
            float* tr = tile + sidx * 129 + c4 * 4;
            tr[0] = a.x - b.x; tr[1] = a.y - b.y; tr[2] = a.z - b.z; tr[3] = a.w - b.w;
        }
        __syncthreads();
#pragma unroll
        for (int it = 0; it < 8; it++) {
            int wi = tid + it * 256;
            int d = wi >> 4, kp = wi & 15;
            float v0 = tile[(2 * kp) * 129 + d], v1 = tile[(2 * kp + 1) * 129 + d];
            size_t dst = ((size_t)g * HD + d) * NSALT + kc * 32 + 2 * kp;
            *(__half2*)(g_vdT + dst) = __floats2half2_rn(v0, v1);
        }
    }
}

// ---------------- K1: fused QK^T + exp + rowsum + delta-PV (1-pass fp16) ----------------
__device__ __forceinline__ void qk_loadK(uint32_t sb, uint32_t buf, int tid, int nt, int s0, int L, int g) {
#pragma unroll
    for (int it = 0; it < 8; it++) {
        int idx = tid + it * 256;
        int r = idx >> 4, ch = idx & 15;
        uint32_t d = (uint32_t)(r * 256) + (((uint32_t)(ch ^ (r & 7))) << 4);
        int jg = nt * 128 + r;
        bool v = jg < L;
        size_t o = v ? (((size_t)(s0 + jg) * NKV + g) * HD + ch * 8) : 0;
        cpa16(sb + buf + d, g_k + o, v);
    }
}

__global__ void __launch_bounds__(256, 2) k_qk(const float* __restrict__ qf,
                                               const float* __restrict__ cc, float* __restrict__ outc) {
    extern __shared__ char dsm[];
    __shared__ int s_sp[SMAXK];
    __shared__ float s_red[64 * 4];
    const int sg = blockIdx.y;
    const int s = sg >> 3, g = sg & 7;
    const int s0 = g_cu[s];
    const int L = g_cu[s + 1] - s0;
    const int mBase = blockIdx.x * 64;
    if (mBase >= 4 * L) return;
    const int salst = g_salst[s], salcnt = g_salcnt[s];

    const int tid = threadIdx.x, wid = tid >> 5, lane = tid & 31;
    const int wm = wid >> 2, wn = wid & 3;
    const uint32_t sb = smem_to_u32(dsm);

    qk_loadK(sb, KB0, tid, 0, s0, L, g);
    CP_COMMIT();
    qk_loadK(sb, KB1, tid, 1, s0, L, g);
    CP_COMMIT();

    for (int j = tid; j < L; j += 256) {
        int sp = g_salpos[s0 + j];
        s_sp[j] = sp >= 0 ? sp - salst : -1;
    }

    // zero Pstage (16KB)
    {
        uint4 z = make_uint4(0, 0, 0, 0);
#pragma unroll
        for (int it = 0; it < 4; it++)
            *(uint4*)(dsm + PSTO + (size_t)(tid + it * 256) * 16) = z;
    }

    // Q tile: fp32 -> fp16(q*SCALE_L2E) single plane, swizzled STS
#pragma unroll
    for (int it = 0; it < 4; it++) {
        int idx = tid + it * 256;
        int r = idx >> 4, ch = idx & 15;
        uint32_t d = (uint32_t)(r * 256) + (((uint32_t)(ch ^ (r & 7))) << 4);
        int mm = mBase + r, il = mm >> 2, hh = mm & 3;
        __half2 h2[4];
        if (il < L) {
            const float4* src = (const float4*)(qf + ((size_t)(s0 + il) * NH + 4 * g + hh) * HD + ch * 8);
            float4 x0 = src[0], x1 = src[1];
            h2[0] = __floats2half2_rn(x0.x * SCALE_L2E, x0.y * SCALE_L2E);
            h2[1] = __floats2half2_rn(x0.z * SCALE_L2E, x0.w * SCALE_L2E);
            h2[2] = __floats2half2_rn(x1.x * SCALE_L2E, x1.y * SCALE_L2E);
            h2[3] = __floats2half2_rn(x1.z * SCALE_L2E, x1.w * SCALE_L2E);
        } else {
            h2[0] = h2[1] = h2[2] = h2[3] = __floats2half2_rn(0.f, 0.f);
        }
        *(uint4*)(dsm + d) = *(uint4*)h2;
    }

    // per-row metadata (Posal base for salient rows)
    ll pb0[2], pb1[2];
    bool ok0[2], ok1[2];
    int rb[2];
#pragma unroll
    for (int mf = 0; mf < 2; mf++) {
        rb[mf] = wm * 32 + mf * 16 + (lane >> 2);
        int mr0 = mBase + rb[mf];
        int mr1 = mr0 + 8;
        int il0 = mr0 >> 2, h0 = mr0 & 3;
        int il1 = mr1 >> 2, h1 = mr1 & 3;
        ok0[mf] = il0 < L; ok1[mf] = il1 < L;
        int sp0 = ok0[mf] ? g_salpos[s0 + il0] : -1;
        int sp1 = ok1[mf] ? g_salpos[s0 + il1] : -1;
        pb0[mf] = sp0 >= 0 ? ((ll)sp0 * NH + 4 * g + h0) * SMAXK : -1;
        pb1[mf] = sp1 >= 0 ? ((ll)sp1 * NH + 4 * g + h1) * SMAXK : -1;
    }

    float rs0[2] = {0.f, 0.f}, rs1[2] = {0.f, 0.f};

    for (int nt = 0; nt < 4; nt++) {
        CP_WAIT1();
        __syncthreads();

        float acc[2][4][4];
#pragma unroll
        for (int a = 0; a < 2; a++)
#pragma unroll
            for (int b = 0; b < 4; b++)
#pragma unroll
                for (int c = 0; c < 4; c++) acc[a][b][c] = 0.f;

        uint32_t buf = (nt & 1) ? KB1 : KB0;
        hmma_1p(sb, QOFF, buf, acc, wid, lane);
        __syncthreads();
        if (nt < 2) {
            qk_loadK(sb, buf, tid, nt + 2, s0, L, g);
            CP_COMMIT();
        } else if (nt == 2) {
#pragma unroll
            for (int it = 0; it < 8; it++) {
                int idx = tid + it * 256;
                int r = idx >> 4, ch = idx & 15;
                uint32_t d = (uint32_t)(r * 256) + (((uint32_t)(ch ^ (r & 7))) << 4);
                bool vb = (ch * 8 < salcnt);
                size_t ib = vb ? (((size_t)(g * HD + r)) * NSALT + salst + ch * 8) : 0;
                cpa16(sb + KB0 + d, g_vdT + ib, vb);
            }
            CP_COMMIT();
        }

#pragma unroll
        for (int nf = 0; nf < 4; nf++) {
            int col = nt * 128 + wn * 32 + nf * 8 + (lane & 3) * 2;
            bool c0 = col < L, c1 = col + 1 < L;
            int spa = c0 ? s_sp[col] : -1;
            int spb = c1 ? s_sp[col + 1] : -1;
#pragma unroll
            for (int mf = 0; mf < 2; mf++) {
                float* c = acc[mf][nf];
                float e0 = (ok0[mf] && c0) ? fexp2(c[0]) : 0.f;
                float e1 = (ok0[mf] && c1) ? fexp2(c[1]) : 0.f;
                float e2 = (ok1[mf] && c0) ? fexp2(c[2]) : 0.f;
                float e3 = (ok1[mf] && c1) ? fexp2(c[3]) : 0.f;
                rs0[mf] += e0 + e1;
                rs1[mf] += e2 + e3;
                int r0 = rb[mf], r1 = r0 + 8;
                if (spa >= 0) {
                    if (ok0[mf]) sts_p(dsm, r0, spa, e0);
                    if (ok1[mf]) sts_p(dsm, r1, spa, e2);
                }
                if (spb >= 0) {
                    if (ok0[mf]) sts_p(dsm, r0, spb, e1);
                    if (ok1[mf]) sts_p(dsm, r1, spb, e3);
                }
                if (pb0[mf] >= 0 && c0)
                    *(__half2*)(g_Posal + pb0[mf] + col) = __floats2half2_rn(e0, e1);
                if (pb1[mf] >= 0 && c0)
                    *(__half2*)(g_Posal + pb1[mf] + col) = __floats2half2_rn(e2, e3);
            }
        }
    }

    // rowsum reduction across n-warps
#pragma unroll
    for (int mf = 0; mf < 2; mf++) {
        rs0[mf] += __shfl_xor_sync(0xffffffffu, rs0[mf], 1);
        rs0[mf] += __shfl_xor_sync(0xffffffffu, rs0[mf], 2);
        rs1[mf] += __shfl_xor_sync(0xffffffffu, rs1[mf], 1);
        rs1[mf] += __shfl_xor_sync(0xffffffffu, rs1[mf], 2);
    }
    if ((lane & 3) == 0) {
#pragma unroll
        for (int mf = 0; mf < 2; mf++) {
            s_red[rb[mf] * 4 + wn] = rs0[mf];
            s_red[(rb[mf] + 8) * 4 + wn] = rs1[mf];
        }
    }
    CP_WAIT0();           // vdT in
    __syncthreads();

    // g_inv for osal
    if (tid < 64) {
        int mm = mBase + tid, il = mm >> 2, h = mm & 3;
        if (il < L) {
            float s4 = s_red[tid * 4] + s_red[tid * 4 + 1] + s_red[tid * 4 + 2] + s_red[tid * 4 + 3];
            g_inv[(size_t)(s0 + il) * NH + 4 * g + h] = 1.f / s4;
        }
    }

    // delta PV: Pstage (A) @ vdT (B @KB0), 1-pass
    float pv[2][4][4];
#pragma unroll
    for (int a = 0; a < 2; a++)
#pragma unroll
        for (int b = 0; b < 4; b++)
#pragma unroll
            for (int c = 0; c < 4; c++) pv[a][b][c] = 0.f;
    hmma_1p(sb, PSTO, KB0, pv, wid, lane);

    // output: non-salient rows only (salient rows overwritten by k_pv)
#pragma unroll
    for (int mf = 0; mf < 2; mf++) {
        int r0 = rb[mf], r1 = r0 + 8;
        int mr0 = mBase + r0, mr1 = mBase + r1;
        int il0 = mr0 >> 2, h0 = mr0 & 3;
        int il1 = mr1 >> 2, h1 = mr1 & 3;
        bool w0 = (il0 < L) && (g_salpos[s0 + il0] < 0);
        bool w1 = (il1 < L) && (g_salpos[s0 + il1] < 0);
        float inv0 = 0.f, inv1 = 0.f;
        if (w0) inv0 = 1.f / (s_red[r0 * 4] + s_red[r0 * 4 + 1] + s_red[r0 * 4 + 2] + s_red[r0 * 4 + 3]);
        if (w1) inv1 = 1.f / (s_red[r1 * 4] + s_red[r1 * 4 + 1] + s_red[r1 * 4 + 2] + s_red[r1 * 4 + 3]);
        size_t id0 = (size_t)(s0 + il0) * NH + 4 * g + h0;
        size_t id1 = (size_t)(s0 + il1) * NH + 4 * g + h1;
#pragma unroll
        for (int nf = 0; nf < 4; nf++) {
            int dcol = wn * 32 + nf * 8 + (lane & 3) * 2;
            float* c = pv[mf][nf];
            if (w0) {
                size_t ob = id0 * HD + dcol;
                float2 cv = *(const float2*)(cc + ob);
                *(float2*)(outc + ob) = make_float2(cv.x + inv0 * c[0], cv.y + inv0 * c[1]);
            }
            if (w1) {
                size_t ob = id1 * HD + dcol;
                float2 cv = *(const float2*)(cc + ob);
                *(float2*)(outc + ob) = make_float2(cv.x + inv1 * c[2], cv.y + inv1 * c[3]);
            }
        }
    }
}

// ---------------- K2: osal: salient rows out = inv * (Posal @ vnT), N-split (64 cols/CTA) ----------------
__global__ void __launch_bounds__(256, 3) k_pv(float* __restrict__ outc) {
    extern __shared__ char dsm[];
    const int sg = blockIdx.y;
    const int s = sg >> 3, g = sg & 7;
    const int s0 = g_cu[s];
    const int L = g_cu[s + 1] - s0;
    const int salst = g_salst[s], salcnt = g_salcnt[s];

    const int tid = threadIdx.x, wid = tid >> 5, lane = tid & 31;
    const int wm = wid >> 2, wn = wid & 3;
    const uint32_t sb = smem_to_u32(dsm);

    const int mBase = (blockIdx.x >> 1) * 64;
    const int nh = blockIdx.x & 1;          // which 64 of the 128 head dims
    if (mBase >= 4 * salcnt) return;

    auto loadA = [&](uint32_t buf, int kc) {
#pragma unroll
        for (int it = 0; it < 4; it++) {
            int idx = tid + it * 256;
            int r = idx >> 4, ch = idx & 15;
            uint32_t d = (uint32_t)(r * 256) + (((uint32_t)(ch ^ (r & 7))) << 4);
            int m = mBase + r, saloc = m >> 2, hh = m & 3;
            int kk = kc * 128 + ch * 8;
            bool va = (saloc < salcnt) && (kk < L);
            size_t ia = va ? (((size_t)(salst + saloc) * NH + 4 * g + hh) * SMAXK + kk) : 0;
            cpa16(sb + buf + d, g_Posal + ia, va);
        }
    };
    auto loadB = [&](uint32_t buf, int kc) {
#pragma unroll
        for (int it = 0; it < 4; it++) {
            int idx = tid + it * 256;
            int r = idx >> 4, ch = idx & 15;   // r in [0,64): local head dim
            uint32_t d = (uint32_t)(r * 256) + (((uint32_t)(ch ^ (r & 7))) << 4);
            int kk = kc * 128 + ch * 8;
            bool vb = (kk < L);
            size_t ib = vb ? (((size_t)(g * HD + nh * 64 + r)) * TT + s0 + kk) : 0;
            cpa16(sb + buf + d, g_vnT + ib, vb);
        }
    };

    const int nkc = (L + 127) / 128;
    loadA(PV_A0, 0); loadB(PV_B0, 0);
    CP_COMMIT();
    if (nkc > 1) { loadA(PV_A1, 1); loadB(PV_B1, 1); }
    CP_COMMIT();

    float acc[2][2][4];
#pragma unroll
    for (int a = 0; a < 2; a++)
#pragma unroll
        for (int b = 0; b < 2; b++)
#pragma unroll
            for (int c = 0; c < 4; c++) acc[a][b][c] = 0.f;

    for (int kc = 0; kc < nkc; kc++) {
        if (kc == nkc - 1) { CP_WAIT0(); } else { CP_WAIT1(); }
        __syncthreads();
        uint32_t aB = (kc & 1) ? PV_A1 : PV_A0;
        uint32_t bB = (kc & 1) ? PV_B1 : PV_B0;
        hmma_n64(sb, aB, bB, acc, wid, lane);
        __syncthreads();
        if (kc + 2 < nkc) {
            loadA(aB, kc + 2); loadB(bB, kc + 2);
            CP_COMMIT();
        }
    }

#pragma unroll
    for (int mf = 0; mf < 2; mf++) {
        int mr0 = mBase + wm * 32 + mf * 16 + (lane >> 2);
        int mr1 = mr0 + 8;
        int sa0 = mr0 >> 2, h0 = mr0 & 3;
        int sa1 = mr1 >> 2, h1 = mr1 & 3;
        bool ok0 = sa0 < salcnt, ok1 = sa1 < salcnt;
        size_t id0 = 0, id1 = 0;
        float inv0 = 0.f, inv1 = 0.f;
        if (ok0) { id0 = (size_t)g_idx[salst + sa0] * NH + 4 * g + h0; inv0 = g_inv[id0]; }
        if (ok1) { id1 = (size_t)g_idx[salst + sa1] * NH + 4 * g + h1; inv1 = g_inv[id1]; }
#pragma unroll
        for (int nf = 0; nf < 2; nf++) {
            int dcol = nh * 64 + wn * 16 + nf * 8 + (lane & 3) * 2;
            float* c = acc[mf][nf];
            if (ok0) *(float2*)(outc + id0 * HD + dcol) = make_float2(inv0 * c[0], inv0 * c[1]);
            if (ok1) *(float2*)(outc + id1 * HD + dcol) = make_float2(inv1 * c[2], inv1 * c[3]);
        }
    }
}

// ---------------- K3: per-row cosine similarity (warp-shuffle reduction) ----------------
__global__ void __launch_bounds__(512) k_cos(const float* __restrict__ cc, const float* __restrict__ outc,
                                             float* __restrict__ cosv) {
    const int tid = threadIdx.x, wid = tid >> 5, lane = tid & 31;
    size_t base = (size_t)blockIdx.x * (NH * HD);
    const float4* a4 = (const float4*)(cc + base);
    const float4* b4 = (const float4*)(outc + base);
    float ab = 0.f, aa = 0.f, bb = 0.f;
#pragma unroll
    for (int j = 0; j < 2; j++) {
        float4 x = a4[tid + j * 512], y = b4[tid + j * 512];
        ab += x.x * y.x + x.y * y.y + x.z * y.z + x.w * y.w;
        aa += x.x * x.x + x.y * x.y + x.z * x.z + x.w * x.w;
        bb += y.x * y.x + y.y * y.y + y.z * y.z + y.w * y.w;
    }
#pragma unroll
    for (int o = 16; o; o >>= 1) {
        ab += __shfl_xor_sync(0xffffffffu, ab, o);
        aa += __shfl_xor_sync(0xffffffffu, aa, o);
        bb += __shfl_xor_sync(0xffffffffu, bb, o);
    }
    __shared__ float sh[3][16];
    if (lane == 0) { sh[0][wid] = ab; sh[1][wid] = aa; sh[2][wid] = bb; }
    __syncthreads();
    if (tid < 32) {
        float a2 = (tid < 16) ? sh[0][tid] : 0.f;
        float b2 = (tid < 16) ? sh[1][tid] : 0.f;
        float c2 = (tid < 16) ? sh[2][tid] : 0.f;
#pragma unroll
        for (int o = 8; o; o >>= 1) {
            a2 += __shfl_xor_sync(0xffffffffu, a2, o);
            b2 += __shfl_xor_sync(0xffffffffu, b2, o);
            c2 += __shfl_xor_sync(0xffffffffu, c2, o);
        }
        if (tid == 0)
            cosv[blockIdx.x] = a2 / (sqrtf(b2) * sqrtf(c2) + 1e-8f);
    }
}

// ---------------- launch ----------------
extern "C" void kernel_launch(void* const* d_in, const int* in_sizes, int n_in,
                              void* d_out, int out_size) {
    const float* q       = (const float*)d_in[0];
    const float* k       = (const float*)d_in[1];
    const float* v       = (const float*)d_in[2];
    const float* v_cache = (const float*)d_in[3];
    const float* c_cache = (const float*)d_in[4];
    const void*  idx     = d_in[5];
    const void*  cu      = d_in[6];

    float* outc = (float*)d_out;
    float* cosv = outc + (size_t)(out_size - TT);

    cudaFuncSetAttribute(k_qk,  cudaFuncAttributeMaxDynamicSharedMemorySize, 98304);
    cudaFuncSetAttribute(k_pv,  cudaFuncAttributeMaxDynamicSharedMemorySize, 65536);
    cudaFuncSetAttribute(k_pre, cudaFuncAttributeMaxDynamicSharedMemorySize, 16512);

    k_prep<<<1, 256>>>(idx, cu);
    k_pre<<<CVT_BLKS + VN_BLKS + VD_BLKS, 256, 16512>>>(k, v, v_cache);
    k_qk<<<dim3(32, 32), 256, 98304>>>(q, c_cache, outc);
    k_pv<<<dim3(16, 32), 256, 65536>>>(outc);
    k_cos<<<TT, 512>>>(c_cache, outc, cosv);
}

// round 16
// speedup vs baseline: 1.0568x; 1.0070x over previous
#include <cuda_runtime.h>
#include <cuda_fp16.h>
#include <math.h>
#include <stdint.h>

typedef unsigned long long ull;
typedef long long ll;

#define TT    2048
#define NH    32
#define NKV   8
#define HD    128
#define NSALT 512
#define NSEG  4
#define SMAXK 512
#define SCALE_L2E 0.12751742788f   /* (1/sqrt(128)) * log2(e), folded into Q */

#define CVT_BLKS 2048
#define VN_BLKS  512
#define VD_BLKS  128

// k_qk smem (64KB): Q[0,16K) KB0[16K,32K) KB1[32K,48K) Pst[48K,64K)
// PV phase: vdT (32KB) -> [16K,48K)
#define QOFF 0u
#define KB0  16384u
#define KB1  32768u
#define PSTO 49152u
// k_pv smem (96KB, R13 layout): A0[0,16K) B0[16K,48K) A1[48K,64K) B1[64K,96K)
#define PV_A0 0u
#define PV_B0 16384u
#define PV_A1 49152u
#define PV_B1 65536u

// ---------------- scratch (device globals: allocation-free) ----------------
__device__ float g_inv[(size_t)TT * NH];
__device__ __half g_k[(size_t)TT * NKV * HD];
__device__ __half g_Posal[(size_t)NSALT * NH * SMAXK];
__device__ __half g_vnT[(size_t)NKV * HD * TT];
__device__ __half g_vdT[(size_t)NKV * HD * NSALT];
__device__ int   g_idx[NSALT];
__device__ int   g_cu[NSEG + 1];
__device__ int   g_salpos[TT];
__device__ int   g_salst[NSEG];
__device__ int   g_salcnt[NSEG];

// ---------------- helpers ----------------
__device__ __forceinline__ uint32_t smem_to_u32(const void* p) {
    uint32_t a;
    asm("{ .reg .u64 t; cvta.to.shared.u64 t, %1; cvt.u32.u64 %0, t; }" : "=r"(a) : "l"(p));
    return a;
}
__device__ __forceinline__ void ldsm4(uint32_t* r, uint32_t addr) {
    asm volatile("ldmatrix.sync.aligned.m8n8.x4.shared.b16 {%0,%1,%2,%3}, [%4];"
        : "=r"(r[0]), "=r"(r[1]), "=r"(r[2]), "=r"(r[3]) : "r"(addr));
}
__device__ __forceinline__ void mma16816(float* c, const uint32_t* a, uint32_t b0, uint32_t b1) {
    asm volatile("mma.sync.aligned.m16n8k16.row.col.f32.f16.f16.f32 "
        "{%0,%1,%2,%3}, {%4,%5,%6,%7}, {%8,%9}, {%0,%1,%2,%3};"
        : "+f"(c[0]), "+f"(c[1]), "+f"(c[2]), "+f"(c[3])
        : "r"(a[0]), "r"(a[1]), "r"(a[2]), "r"(a[3]), "r"(b0), "r"(b1));
}
__device__ __forceinline__ void cpa16(uint32_t dst, const void* src, bool valid) {
    int sz = valid ? 16 : 0;
    asm volatile("cp.async.cg.shared.global [%0], [%1], 16, %2;"
        :: "r"(dst), "l"(src), "r"(sz) : "memory");
}
#define CP_COMMIT() asm volatile("cp.async.commit_group;" ::: "memory")
#define CP_WAIT0()  asm volatile("cp.async.wait_group 0;" ::: "memory")
#define CP_WAIT1()  asm volatile("cp.async.wait_group 1;" ::: "memory")

__device__ __forceinline__ float fexp2(float x) {
    float r;
    asm("ex2.approx.f32 %0, %1;" : "=f"(r) : "f"(x));
    return r;
}

// 64(m)x128(n)x128(k) 1-pass fp16 HMMA (k_pv). A @aOff; B @bOff. acc[2][4][4].
__device__ __forceinline__ void hmma_1p(uint32_t sb, uint32_t aOff, uint32_t bOff,
                                        float acc[2][4][4], int wid, int lane) {
    const int wm = wid >> 2, wn = wid & 3;
    uint32_t a_ad[2], a_rx[2];
#pragma unroll
    for (int mf = 0; mf < 2; mf++) {
        int row = wm * 32 + mf * 16 + (lane & 15);
        a_ad[mf] = sb + aOff + row * 256;
        a_rx[mf] = ((uint32_t)(row & 7)) << 4;
    }
    const int achunk = (lane >> 4);
    uint32_t b_ad[2], b_rx[2];
#pragma unroll
    for (int bg = 0; bg < 2; bg++) {
        int n = wn * 32 + bg * 16 + (lane & 7) + ((lane >> 4) << 3);
        b_ad[bg] = sb + bOff + n * 256;
        b_rx[bg] = ((uint32_t)(n & 7)) << 4;
    }
    const int bchunk = (lane >> 3) & 1;
#pragma unroll
    for (int ks = 0; ks < 8; ks++) {
        uint32_t ah[2][4];
#pragma unroll
        for (int mf = 0; mf < 2; mf++) {
            uint32_t coff = (((uint32_t)(ks * 2 + achunk)) << 4) ^ a_rx[mf];
            ldsm4(ah[mf], a_ad[mf] + coff);
        }
        uint32_t bh[2][4];
#pragma unroll
        for (int bg = 0; bg < 2; bg++) {
            uint32_t coff = (((uint32_t)(ks * 2 + bchunk)) << 4) ^ b_rx[bg];
            ldsm4(bh[bg], b_ad[bg] + coff);
        }
#pragma unroll
        for (int mf = 0; mf < 2; mf++)
#pragma unroll
            for (int nf = 0; nf < 4; nf++) {
                int bg = nf >> 1, sel = (nf & 1) * 2;
                mma16816(acc[mf][nf], ah[mf], bh[bg][sel], bh[bg][sel + 1]);
            }
    }
}

// 64(m)x64(n)x128(k) 1-pass fp16 HMMA. Verified geometry (R12 hmma_qk2 minus lo).
__device__ __forceinline__ void hmma_n64(uint32_t sb, uint32_t aOff, uint32_t bOff,
                                         float acc[2][2][4], int wid, int lane) {
    const int wm = wid >> 2, wn = wid & 3;
    uint32_t a_ad[2], a_rx[2];
#pragma unroll
    for (int mf = 0; mf < 2; mf++) {
        int row = wm * 32 + mf * 16 + (lane & 15);
        a_ad[mf] = sb + aOff + row * 256;
        a_rx[mf] = ((uint32_t)(row & 7)) << 4;
    }
    const int achunk = (lane >> 4);
    int n = wn * 16 + (lane & 7) + ((lane >> 4) << 3);
    uint32_t b_ad = sb + bOff + n * 256;
    uint32_t b_rx = ((uint32_t)(n & 7)) << 4;
    const int bchunk = (lane >> 3) & 1;
#pragma unroll
    for (int ks = 0; ks < 8; ks++) {
        uint32_t ah[2][4];
#pragma unroll
        for (int mf = 0; mf < 2; mf++) {
            uint32_t coff = (((uint32_t)(ks * 2 + achunk)) << 4) ^ a_rx[mf];
            ldsm4(ah[mf], a_ad[mf] + coff);
        }
        uint32_t bh[4];
        {
            uint32_t coff = (((uint32_t)(ks * 2 + bchunk)) << 4) ^ b_rx;
            ldsm4(bh, b_ad + coff);
        }
#pragma unroll
        for (int mf = 0; mf < 2; mf++)
#pragma unroll
            for (int nf = 0; nf < 2; nf++) {
                int sel = nf * 2;
                mma16816(acc[mf][nf], ah[mf], bh[sel], bh[sel + 1]);
            }
    }
}

// store one P value into swizzled Pstage (single fp16 plane @PSTO)
__device__ __forceinline__ void sts_p(char* dsm, int row, int salcol, float val) {
    uint32_t off = (uint32_t)row * 256 + ((((uint32_t)(salcol >> 3)) ^ (uint32_t)(row & 7)) << 4)
                 + (uint32_t)((2 * salcol) & 15);
    *(__half*)(dsm + PSTO + off) = __float2half_rn(val);
}

// ---------------- K0a: decode indices, segment tables ----------------
__global__ void k_prep(const void* idx_raw, const void* cu_raw) {
    const int* i32 = (const int*)idx_raw;
    const int* c32 = (const int*)cu_raw;
    const bool idx64 = (i32[1] == 0);
    const bool cu64  = (c32[1] == 0);
    const int t = threadIdx.x;

    for (int i = t; i < NSALT; i += 256)
        g_idx[i] = idx64 ? (int)((const long long*)idx_raw)[i] : i32[i];
    if (t <= NSEG)
        g_cu[t] = cu64 ? (int)((const long long*)cu_raw)[t] : c32[t];
    for (int i = t; i < TT; i += 256) g_salpos[i] = -1;
    __syncthreads();
    for (int i = t; i < NSALT; i += 256) g_salpos[g_idx[i]] = i;
    if (t == 0) {
        for (int s = 0; s < NSEG; s++) {
            int a = 0;
            while (a < NSALT && g_idx[a] < g_cu[s]) a++;
            int b = a;
            while (b < NSALT && g_idx[b] < g_cu[s + 1]) b++;
            g_salst[s] = a;
            g_salcnt[s] = b - a;
        }
    }
}

// ---------------- K0b (merged): K cvt || build_vn || build_vd (single fp16) ----------------
__global__ void __launch_bounds__(256) k_pre(const float* __restrict__ kk,
                                             const float* __restrict__ v, const float* __restrict__ vc) {
    extern __shared__ float tile[];   // [32][129]
    const int bx = blockIdx.x;
    const int tid = threadIdx.x;

    if (bx < CVT_BLKS) {
        int i = bx * 256 + tid;
        float4 x = ((const float4*)kk)[i];
        __half2 h2[2];
        h2[0] = __floats2half2_rn(x.x, x.y);
        h2[1] = __floats2half2_rn(x.z, x.w);
        *(uint2*)(g_k + 4 * (size_t)i) = *(uint2*)h2;
        return;
    }

    if (bx < CVT_BLKS + VN_BLKS) {
        int t2 = bx - CVT_BLKS;
        int kc = t2 >> 3, g = t2 & 7;
#pragma unroll
        for (int it = 0; it < 4; it++) {
            int fi = tid + it * 256;
            int key = fi >> 5, c4 = fi & 31;
            int gk = kc * 32 + key;
            int sp = g_salpos[gk];
            const float* src = (sp >= 0) ? v + ((size_t)sp * NKV + g) * HD + c4 * 4
                                         : vc + ((size_t)gk * NKV + g) * HD + c4 * 4;
            float4 x = *(const float4*)src;
            float* tr = tile + key * 129 + c4 * 4;
            tr[0] = x.x; tr[1] = x.y; tr[2] = x.z; tr[3] = x.w;
        }
        __syncthreads();
#pragma unroll
        for (int it = 0; it < 8; it++) {
            int wi = tid + it * 256;
            int d = wi >> 4, kp = wi & 15;
            float v0 = tile[(2 * kp) * 129 + d], v1 = tile[(2 * kp + 1) * 129 + d];
            size_t dst = ((size_t)g * HD + d) * TT + kc * 32 + 2 * kp;
            *(__half2*)(g_vnT + dst) = __floats2half2_rn(v0, v1);
        }
        return;
    }

    {
        int t2 = bx - CVT_BLKS - VN_BLKS;
        int kc = t2 >> 3, g = t2 & 7;
#pragma unroll
        for (int it = 0; it < 4; it++) {
            int fi = tid + it * 256;
            int sidx = fi >> 5, c4 = fi & 31;
            int sal = kc * 32 + sidx;
            const float* pv = v  + ((size_t)sal * NKV + g) * HD + c4 * 4;
            const float* pc = vc + ((size_t)g_idx[sal] * NKV + g) * HD + c4 * 4;
            float4 a = *(const float4*)pv;
            float4 b = *(const float4*)pc;
            float* tr = tile + sidx * 129 + c4 * 4;
            tr[0] = a.x - b.x; tr[1] = a.y - b.y; tr[2] = a.z - b.z; tr[3] = a.w - b.w;
        }
        __syncthreads();
#pragma unroll
        for (int it = 0; it < 8; it++) {
            int wi = tid + it * 256;
            int d = wi >> 4, kp = wi & 15;
            float v0 = tile[(2 * kp) * 129 + d], v1 = tile[(2 * kp + 1) * 129 + d];
            size_t dst = ((size_t)g * HD + d) * NSALT + kc * 32 + 2 * kp;
            *(__half2*)(g_vdT + dst) = __floats2half2_rn(v0, v1);
        }
    }
}

// ---------------- K1: fused QK^T + exp + rowsum + delta-PV (64KB smem, 3 CTA/SM) ----------------
__device__ __forceinline__ void qk_loadK64(uint32_t sb, uint32_t buf, int tid, int nt, int s0, int L, int g) {
#pragma unroll
    for (int it = 0; it < 4; it++) {
        int idx = tid + it * 256;
        int r = idx >> 4, ch = idx & 15;
        uint32_t d = (uint32_t)(r * 256) + (((uint32_t)(ch ^ (r & 7))) << 4);
        int jg = nt * 64 + r;
        bool v = jg < L;
        size_t o = v ? (((size_t)(s0 + jg) * NKV + g) * HD + ch * 8) : 0;
        cpa16(sb + buf + d, g_k + o, v);
    }
}

__global__ void __launch_bounds__(256, 3) k_qk(const float* __restrict__ qf,
                                               const float* __restrict__ cc, float* __restrict__ outc) {
    extern __shared__ char dsm[];
    __shared__ int s_sp[SMAXK];
    __shared__ float s_red[64 * 4];
    const int sg = blockIdx.y;
    const int s = sg >> 3, g = sg & 7;
    const int s0 = g_cu[s];
    const int L = g_cu[s + 1] - s0;
    const int mBase = blockIdx.x * 64;
    if (mBase >= 4 * L) return;
    const int salst = g_salst[s], salcnt = g_salcnt[s];

    const int tid = threadIdx.x, wid = tid >> 5, lane = tid & 31;
    const int wm = wid >> 2, wn = wid & 3;
    const uint32_t sb = smem_to_u32(dsm);

    qk_loadK64(sb, KB0, tid, 0, s0, L, g);
    CP_COMMIT();
    qk_loadK64(sb, KB1, tid, 1, s0, L, g);
    CP_COMMIT();

    for (int j = tid; j < L; j += 256) {
        int sp = g_salpos[s0 + j];
        s_sp[j] = sp >= 0 ? sp - salst : -1;
    }

    // zero Pstage (16KB)
    {
        uint4 z = make_uint4(0, 0, 0, 0);
#pragma unroll
        for (int it = 0; it < 4; it++)
            *(uint4*)(dsm + PSTO + (size_t)(tid + it * 256) * 16) = z;
    }

    // Q tile: fp32 -> fp16(q*SCALE_L2E) single plane, swizzled STS
#pragma unroll
    for (int it = 0; it < 4; it++) {
        int idx = tid + it * 256;
        int r = idx >> 4, ch = idx & 15;
        uint32_t d = (uint32_t)(r * 256) + (((uint32_t)(ch ^ (r & 7))) << 4);
        int mm = mBase + r, il = mm >> 2, hh = mm & 3;
        __half2 h2[4];
        if (il < L) {
            const float4* src = (const float4*)(qf + ((size_t)(s0 + il) * NH + 4 * g + hh) * HD + ch * 8);
            float4 x0 = src[0], x1 = src[1];
            h2[0] = __floats2half2_rn(x0.x * SCALE_L2E, x0.y * SCALE_L2E);
            h2[1] = __floats2half2_rn(x0.z * SCALE_L2E, x0.w * SCALE_L2E);
            h2[2] = __floats2half2_rn(x1.x * SCALE_L2E, x1.y * SCALE_L2E);
            h2[3] = __floats2half2_rn(x1.z * SCALE_L2E, x1.w * SCALE_L2E);
        } else {
            h2[0] = h2[1] = h2[2] = h2[3] = __floats2half2_rn(0.f, 0.f);
        }
        *(uint4*)(dsm + d) = *(uint4*)h2;
    }

    // per-row metadata (Posal base for salient rows)
    ll pb0[2], pb1[2];
    bool ok0[2], ok1[2];
    int rb[2];
#pragma unroll
    for (int mf = 0; mf < 2; mf++) {
        rb[mf] = wm * 32 + mf * 16 + (lane >> 2);
        int mr0 = mBase + rb[mf];
        int mr1 = mr0 + 8;
        int il0 = mr0 >> 2, h0 = mr0 & 3;
        int il1 = mr1 >> 2, h1 = mr1 & 3;
        ok0[mf] = il0 < L; ok1[mf] = il1 < L;
        int sp0 = ok0[mf] ? g_salpos[s0 + il0] : -1;
        int sp1 = ok1[mf] ? g_salpos[s0 + il1] : -1;
        pb0[mf] = sp0 >= 0 ? ((ll)sp0 * NH + 4 * g + h0) * SMAXK : -1;
        pb1[mf] = sp1 >= 0 ? ((ll)sp1 * NH + 4 * g + h1) * SMAXK : -1;
    }

    float rs0[2] = {0.f, 0.f}, rs1[2] = {0.f, 0.f};

    for (int nt = 0; nt < 8; nt++) {
        if (nt == 7) { CP_WAIT0(); } else { CP_WAIT1(); }
        __syncthreads();

        float acc[2][2][4];
#pragma unroll
        for (int a = 0; a < 2; a++)
#pragma unroll
            for (int b = 0; b < 2; b++)
#pragma unroll
                for (int c = 0; c < 4; c++) acc[a][b][c] = 0.f;

        uint32_t buf = (nt & 1) ? KB1 : KB0;
        hmma_n64(sb, QOFF, buf, acc, wid, lane);
        __syncthreads();
        if (nt < 6) {
            qk_loadK64(sb, buf, tid, nt + 2, s0, L, g);
            CP_COMMIT();
        }

        // epilogue: exp (scale pre-folded), rowsum, Pstage STS, Posal STG
#pragma unroll
        for (int nf = 0; nf < 2; nf++) {
            int col = nt * 64 + wn * 16 + nf * 8 + (lane & 3) * 2;
            bool c0 = col < L, c1 = col + 1 < L;
            int spa = c0 ? s_sp[col] : -1;
            int spb = c1 ? s_sp[col + 1] : -1;
#pragma unroll
            for (int mf = 0; mf < 2; mf++) {
                float* c = acc[mf][nf];
                float e0 = (ok0[mf] && c0) ? fexp2(c[0]) : 0.f;
                float e1 = (ok0[mf] && c1) ? fexp2(c[1]) : 0.f;
                float e2 = (ok1[mf] && c0) ? fexp2(c[2]) : 0.f;
                float e3 = (ok1[mf] && c1) ? fexp2(c[3]) : 0.f;
                rs0[mf] += e0 + e1;
                rs1[mf] += e2 + e3;
                int r0 = rb[mf], r1 = r0 + 8;
                if (spa >= 0) {
                    if (ok0[mf]) sts_p(dsm, r0, spa, e0);
                    if (ok1[mf]) sts_p(dsm, r1, spa, e2);
                }
                if (spb >= 0) {
                    if (ok0[mf]) sts_p(dsm, r0, spb, e1);
                    if (ok1[mf]) sts_p(dsm, r1, spb, e3);
                }
                if (pb0[mf] >= 0 && c0)
                    *(__half2*)(g_Posal + pb0[mf] + col) = __floats2half2_rn(e0, e1);
                if (pb1[mf] >= 0 && c0)
                    *(__half2*)(g_Posal + pb1[mf] + col) = __floats2half2_rn(e2, e3);
            }
        }
    }

    // vdT (32KB) -> [16K,48K): both K buffers now free
#pragma unroll
    for (int it = 0; it < 8; it++) {
        int idx = tid + it * 256;
        int r = idx >> 4, ch = idx & 15;
        uint32_t d = (uint32_t)(r * 256) + (((uint32_t)(ch ^ (r & 7))) << 4);
        bool vb = (ch * 8 < salcnt);
        size_t ib = vb ? (((size_t)(g * HD + r)) * NSALT + salst + ch * 8) : 0;
        cpa16(sb + KB0 + d, g_vdT + ib, vb);
    }
    CP_COMMIT();

    // rowsum reduction across n-warps (overlaps vdT load)
#pragma unroll
    for (int mf = 0; mf < 2; mf++) {
        rs0[mf] += __shfl_xor_sync(0xffffffffu, rs0[mf], 1);
        rs0[mf] += __shfl_xor_sync(0xffffffffu, rs0[mf], 2);
        rs1[mf] += __shfl_xor_sync(0xffffffffu, rs1[mf], 1);
        rs1[mf] += __shfl_xor_sync(0xffffffffu, rs1[mf], 2);
    }
    if ((lane & 3) == 0) {
#pragma unroll
        for (int mf = 0; mf < 2; mf++) {
            s_red[rb[mf] * 4 + wn] = rs0[mf];
            s_red[(rb[mf] + 8) * 4 + wn] = rs1[mf];
        }
    }
    CP_WAIT0();
    __syncthreads();

    // g_inv for osal
    if (tid < 64) {
        int mm = mBase + tid, il = mm >> 2, h = mm & 3;
        if (il < L) {
            float s4 = s_red[tid * 4] + s_red[tid * 4 + 1] + s_red[tid * 4 + 2] + s_red[tid * 4 + 3];
            g_inv[(size_t)(s0 + il) * NH + 4 * g + h] = 1.f / s4;
        }
    }

    // per-row inv + write mask (salient rows overwritten by k_pv)
    float inv0[2], inv1[2];
    bool w0[2], w1[2];
    size_t id0[2], id1[2];
#pragma unroll
    for (int mf = 0; mf < 2; mf++) {
        int r0 = rb[mf], r1 = r0 + 8;
        int mr0 = mBase + r0, mr1 = mBase + r1;
        int il0 = mr0 >> 2, h0 = mr0 & 3;
        int il1 = mr1 >> 2, h1 = mr1 & 3;
        w0[mf] = (il0 < L) && (pb0[mf] < 0);
        w1[mf] = (il1 < L) && (pb1[mf] < 0);
        inv0[mf] = w0[mf] ? 1.f / (s_red[r0 * 4] + s_red[r0 * 4 + 1] + s_red[r0 * 4 + 2] + s_red[r0 * 4 + 3]) : 0.f;
        inv1[mf] = w1[mf] ? 1.f / (s_red[r1 * 4] + s_red[r1 * 4 + 1] + s_red[r1 * 4 + 2] + s_red[r1 * 4 + 3]) : 0.f;
        id0[mf] = (size_t)(s0 + il0) * NH + 4 * g + h0;
        id1[mf] = (size_t)(s0 + il1) * NH + 4 * g + h1;
    }

    // delta PV in two N=64 halves (register-light for occ 3)
#pragma unroll
    for (int ph = 0; ph < 2; ph++) {
        float pv[2][2][4];
#pragma unroll
        for (int a = 0; a < 2; a++)
#pragma unroll
            for (int b = 0; b < 2; b++)
#pragma unroll
                for (int c = 0; c < 4; c++) pv[a][b][c] = 0.f;
        hmma_n64(sb, PSTO, KB0 + (uint32_t)ph * 16384u, pv, wid, lane);

#pragma unroll
        for (int mf = 0; mf < 2; mf++) {
#pragma unroll
            for (int nf = 0; nf < 2; nf++) {
                int dcol = ph * 64 + wn * 16 + nf * 8 + (lane & 3) * 2;
                float* c = pv[mf][nf];
                if (w0[mf]) {
                    size_t ob = id0[mf] * HD + dcol;
                    float2 cv = *(const float2*)(cc + ob);
                    *(float2*)(outc + ob) = make_float2(cv.x + inv0[mf] * c[0], cv.y + inv0[mf] * c[1]);
                }
                if (w1[mf]) {
                    size_t ob = id1[mf] * HD + dcol;
                    float2 cv = *(const float2*)(cc + ob);
                    *(float2*)(outc + ob) = make_float2(cv.x + inv1[mf] * c[2], cv.y + inv1[mf] * c[3]);
                }
            }
        }
    }
}

// ---------------- K2: osal (R13 version): salient rows out = inv * (Posal @ vnT) ----------------
__global__ void __launch_bounds__(256, 2) k_pv(float* __restrict__ outc) {
    extern __shared__ char dsm[];
    const int sg = blockIdx.y;
    const int s = sg >> 3, g = sg & 7;
    const int s0 = g_cu[s];
    const int L = g_cu[s + 1] - s0;
    const int salst = g_salst[s], salcnt = g_salcnt[s];

    const int tid = threadIdx.x, wid = tid >> 5, lane = tid & 31;
    const int wm = wid >> 2, wn = wid & 3;
    const uint32_t sb = smem_to_u32(dsm);

    const int mBase = blockIdx.x * 64;
    if (mBase >= 4 * salcnt) return;

    auto loadA = [&](uint32_t buf, int kc) {
#pragma unroll
        for (int it = 0; it < 4; it++) {
            int idx = tid + it * 256;
            int r = idx >> 4, ch = idx & 15;
            uint32_t d = (uint32_t)(r * 256) + (((uint32_t)(ch ^ (r & 7))) << 4);
            int m = mBase + r, saloc = m >> 2, hh = m & 3;
            int kk = kc * 128 + ch * 8;
            bool va = (saloc < salcnt) && (kk < L);
            size_t ia = va ? (((size_t)(salst + saloc) * NH + 4 * g + hh) * SMAXK + kk) : 0;
            cpa16(sb + buf + d, g_Posal + ia, va);
        }
    };
    auto loadB = [&](uint32_t buf, int kc) {
#pragma unroll
        for (int it = 0; it < 8; it++) {
            int idx = tid + it * 256;
            int r = idx >> 4, ch = idx & 15;
            uint32_t d = (uint32_t)(r * 256) + (((uint32_t)(ch ^ (r & 7))) << 4);
            int kk = kc * 128 + ch * 8;
            bool vb = (kk < L);
            size_t ib = vb ? (((size_t)(g * HD + r)) * TT + s0 + kk) : 0;
            cpa16(sb + buf + d, g_vnT + ib, vb);
        }
    };

    const int nkc = (L + 127) / 128;
    loadA(PV_A0, 0); loadB(PV_B0, 0);
    CP_COMMIT();
    if (nkc > 1) { loadA(PV_A1, 1); loadB(PV_B1, 1); }
    CP_COMMIT();

    float acc[2][4][4];
#pragma unroll
    for (int a = 0; a < 2; a++)
#pragma unroll
        for (int b = 0; b < 4; b++)
#pragma unroll
            for (int c = 0; c < 4; c++) acc[a][b][c] = 0.f;

    for (int kc = 0; kc < nkc; kc++) {
        if (kc == nkc - 1) { CP_WAIT0(); } else { CP_WAIT1(); }
        __syncthreads();
        uint32_t aB = (kc & 1) ? PV_A1 : PV_A0;
        uint32_t bB = (kc & 1) ? PV_B1 : PV_B0;
        hmma_1p(sb, aB, bB, acc, wid, lane);
        __syncthreads();
        if (kc + 2 < nkc) {
            loadA(aB, kc + 2); loadB(bB, kc + 2);
            CP_COMMIT();
        }
    }

#pragma unroll
    for (int mf = 0; mf < 2; mf++) {
        int mr0 = mBase + wm * 32 + mf * 16 + (lane >> 2);
        int mr1 = mr0 + 8;
        int sa0 = mr0 >> 2, h0 = mr0 & 3;
        int sa1 = mr1 >> 2, h1 = mr1 & 3;
        bool ok0 = sa0 < salcnt, ok1 = sa1 < salcnt;
        size_t id0 = 0, id1 = 0;
        float inv0 = 0.f, inv1 = 0.f;
        if (ok0) { id0 = (size_t)g_idx[salst + sa0] * NH + 4 * g + h0; inv0 = g_inv[id0]; }
        if (ok1) { id1 = (size_t)g_idx[salst + sa1] * NH + 4 * g + h1; inv1 = g_inv[id1]; }
#pragma unroll
        for (int nf = 0; nf < 4; nf++) {
            int dcol = wn * 32 + nf * 8 + (lane & 3) * 2;
            float* c = acc[mf][nf];
            if (ok0) *(float2*)(outc + id0 * HD + dcol) = make_float2(inv0 * c[0], inv0 * c[1]);
            if (ok1) *(float2*)(outc + id1 * HD + dcol) = make_float2(inv1 * c[2], inv1 * c[3]);
        }
    }
}

// ---------------- K3: per-row cosine similarity (warp-shuffle reduction) ----------------
__global__ void __launch_bounds__(512) k_cos(const float* __restrict__ cc, const float* __restrict__ outc,
                                             float* __restrict__ cosv) {
    const int tid = threadIdx.x, wid = tid >> 5, lane = tid & 31;
    size_t base = (size_t)blockIdx.x * (NH * HD);
    const float4* a4 = (const float4*)(cc + base);
    const float4* b4 = (const float4*)(outc + base);
    float ab = 0.f, aa = 0.f, bb = 0.f;
#pragma unroll
    for (int j = 0; j < 2; j++) {
        float4 x = a4[tid + j * 512], y = b4[tid + j * 512];
        ab += x.x * y.x + x.y * y.y + x.z * y.z + x.w * y.w;
        aa += x.x * x.x + x.y * x.y + x.z * x.z + x.w * x.w;
        bb += y.x * y.x + y.y * y.y + y.z * y.z + y.w * y.w;
    }
#pragma unroll
    for (int o = 16; o; o >>= 1) {
        ab += __shfl_xor_sync(0xffffffffu, ab, o);
        aa += __shfl_xor_sync(0xffffffffu, aa, o);
        bb += __shfl_xor_sync(0xffffffffu, bb, o);
    }
    __shared__ float sh[3][16];
    if (lane == 0) { sh[0][wid] = ab; sh[1][wid] = aa; sh[2][wid] = bb; }
    __syncthreads();
    if (tid < 32) {
        float a2 = (tid < 16) ? sh[0][tid] : 0.f;
        float b2 = (tid < 16) ? sh[1][tid] : 0.f;
        float c2 = (tid < 16) ? sh[2][tid] : 0.f;
#pragma unroll
        for (int o = 8; o; o >>= 1) {
            a2 += __shfl_xor_sync(0xffffffffu, a2, o);
            b2 += __shfl_xor_sync(0xffffffffu, b2, o);
            c2 += __shfl_xor_sync(0xffffffffu, c2, o);
        }
        if (tid == 0)
            cosv[blockIdx.x] = a2 / (sqrtf(b2) * sqrtf(c2) + 1e-8f);
    }
}

// ---------------- launch ----------------
extern "C" void kernel_launch(void* const* d_in, const int* in_sizes, int n_in,
                              void* d_out, int out_size) {
    const float* q       = (const float*)d_in[0];
    const float* k       = (const float*)d_in[1];
    const float* v       = (const float*)d_in[2];
    const float* v_cache = (const float*)d_in[3];
    const float* c_cache = (const float*)d_in[4];
    const void*  idx     = d_in[5];
    const void*  cu      = d_in[6];

    float* outc = (float*)d_out;
    float* cosv = outc + (size_t)(out_size - TT);

    cudaFuncSetAttribute(k_qk,  cudaFuncAttributeMaxDynamicSharedMemorySize, 65536);
    cudaFuncSetAttribute(k_pv,  cudaFuncAttributeMaxDynamicSharedMemorySize, 98304);
    cudaFuncSetAttribute(k_pre, cudaFuncAttributeMaxDynamicSharedMemorySize, 16512);

    k_prep<<<1, 256>>>(idx, cu);
    k_pre<<<CVT_BLKS + VN_BLKS + VD_BLKS, 256, 16512>>>(k, v, v_cache);
    k_qk<<<dim3(32, 32), 256, 65536>>>(q, c_cache, outc);
    k_pv<<<dim3(8, 32), 256, 98304>>>(outc);
    k_cos<<<TT, 512>>>(c_cache, outc, cosv);
}

// round 17
// speedup vs baseline: 1.2218x; 1.1562x over previous
#include <cuda_runtime.h>
#include <cuda_fp16.h>
#include <math.h>
#include <stdint.h>

typedef unsigned long long ull;
typedef long long ll;

#define TT    2048
#define NH    32
#define NKV   8
#define HD    128
#define NSALT 512
#define NSEG  4
#define SMAXK 512
#define SCALE_L2E 0.12751742788f   /* (1/sqrt(128)) * log2(e), folded into Q */

#define CVT_BLKS 2048
#define VN_BLKS  512
#define VD_BLKS  128

// k_qk smem (64KB): Q[0,16K) KB0[16K,32K) KB1[32K,48K) Pst[48K,64K)
// PV phase: vdT (32KB) -> [16K,48K)
#define QOFF 0u
#define KB0  16384u
#define KB1  32768u
#define PSTO 49152u
// k_pv smem (96KB): A0[0,16K) B0[16K,48K) A1[48K,64K) B1[64K,96K)
#define PV_A0 0u
#define PV_B0 16384u
#define PV_A1 49152u
#define PV_B1 65536u

// ---------------- scratch (device globals: allocation-free) ----------------
__device__ float g_inv[(size_t)TT * NH];
__device__ __half g_k[(size_t)TT * NKV * HD];
__device__ __half g_Posal[(size_t)NSALT * NH * SMAXK];
__device__ __half g_vnT[(size_t)NKV * HD * TT];
__device__ __half g_vdT[(size_t)NKV * HD * NSALT];
__device__ int   g_idx[NSALT];
__device__ int   g_cu[NSEG + 1];
__device__ int   g_salpos[TT];
__device__ int   g_salst[NSEG];
__device__ int   g_salcnt[NSEG];

// ---------------- helpers ----------------
__device__ __forceinline__ uint32_t smem_to_u32(const void* p) {
    uint32_t a;
    asm("{ .reg .u64 t; cvta.to.shared.u64 t, %1; cvt.u32.u64 %0, t; }" : "=r"(a) : "l"(p));
    return a;
}
__device__ __forceinline__ void ldsm4(uint32_t* r, uint32_t addr) {
    asm volatile("ldmatrix.sync.aligned.m8n8.x4.shared.b16 {%0,%1,%2,%3}, [%4];"
        : "=r"(r[0]), "=r"(r[1]), "=r"(r[2]), "=r"(r[3]) : "r"(addr));
}
__device__ __forceinline__ void mma16816(float* c, const uint32_t* a, uint32_t b0, uint32_t b1) {
    asm volatile("mma.sync.aligned.m16n8k16.row.col.f32.f16.f16.f32 "
        "{%0,%1,%2,%3}, {%4,%5,%6,%7}, {%8,%9}, {%0,%1,%2,%3};"
        : "+f"(c[0]), "+f"(c[1]), "+f"(c[2]), "+f"(c[3])
        : "r"(a[0]), "r"(a[1]), "r"(a[2]), "r"(a[3]), "r"(b0), "r"(b1));
}
__device__ __forceinline__ void cpa16(uint32_t dst, const void* src, bool valid) {
    int sz = valid ? 16 : 0;
    asm volatile("cp.async.cg.shared.global [%0], [%1], 16, %2;"
        :: "r"(dst), "l"(src), "r"(sz) : "memory");
}
#define CP_COMMIT() asm volatile("cp.async.commit_group;" ::: "memory")
#define CP_WAIT0()  asm volatile("cp.async.wait_group 0;" ::: "memory")
#define CP_WAIT1()  asm volatile("cp.async.wait_group 1;" ::: "memory")

__device__ __forceinline__ float fexp2(float x) {
    float r;
    asm("ex2.approx.f32 %0, %1;" : "=f"(r) : "f"(x));
    return r;
}

// 64(m)x128(n)x128(k) 1-pass fp16 HMMA (k_pv). A @aOff; B @bOff. acc[2][4][4].
__device__ __forceinline__ void hmma_1p(uint32_t sb, uint32_t aOff, uint32_t bOff,
                                        float acc[2][4][4], int wid, int lane) {
    const int wm = wid >> 2, wn = wid & 3;
    uint32_t a_ad[2], a_rx[2];
#pragma unroll
    for (int mf = 0; mf < 2; mf++) {
        int row = wm * 32 + mf * 16 + (lane & 15);
        a_ad[mf] = sb + aOff + row * 256;
        a_rx[mf] = ((uint32_t)(row & 7)) << 4;
    }
    const int achunk = (lane >> 4);
    uint32_t b_ad[2], b_rx[2];
#pragma unroll
    for (int bg = 0; bg < 2; bg++) {
        int n = wn * 32 + bg * 16 + (lane & 7) + ((lane >> 4) << 3);
        b_ad[bg] = sb + bOff + n * 256;
        b_rx[bg] = ((uint32_t)(n & 7)) << 4;
    }
    const int bchunk = (lane >> 3) & 1;
#pragma unroll
    for (int ks = 0; ks < 8; ks++) {
        uint32_t ah[2][4];
#pragma unroll
        for (int mf = 0; mf < 2; mf++) {
            uint32_t coff = (((uint32_t)(ks * 2 + achunk)) << 4) ^ a_rx[mf];
            ldsm4(ah[mf], a_ad[mf] + coff);
        }
        uint32_t bh[2][4];
#pragma unroll
        for (int bg = 0; bg < 2; bg++) {
            uint32_t coff = (((uint32_t)(ks * 2 + bchunk)) << 4) ^ b_rx[bg];
            ldsm4(bh[bg], b_ad[bg] + coff);
        }
#pragma unroll
        for (int mf = 0; mf < 2; mf++)
#pragma unroll
            for (int nf = 0; nf < 4; nf++) {
                int bg = nf >> 1, sel = (nf & 1) * 2;
                mma16816(acc[mf][nf], ah[mf], bh[bg][sel], bh[bg][sel + 1]);
            }
    }
}

// 64(m)x64(n)x128(k) 1-pass fp16 HMMA. Verified geometry (R12 hmma_qk2 minus lo).
__device__ __forceinline__ void hmma_n64(uint32_t sb, uint32_t aOff, uint32_t bOff,
                                         float acc[2][2][4], int wid, int lane) {
    const int wm = wid >> 2, wn = wid & 3;
    uint32_t a_ad[2], a_rx[2];
#pragma unroll
    for (int mf = 0; mf < 2; mf++) {
        int row = wm * 32 + mf * 16 + (lane & 15);
        a_ad[mf] = sb + aOff + row * 256;
        a_rx[mf] = ((uint32_t)(row & 7)) << 4;
    }
    const int achunk = (lane >> 4);
    int n = wn * 16 + (lane & 7) + ((lane >> 4) << 3);
    uint32_t b_ad = sb + bOff + n * 256;
    uint32_t b_rx = ((uint32_t)(n & 7)) << 4;
    const int bchunk = (lane >> 3) & 1;
#pragma unroll
    for (int ks = 0; ks < 8; ks++) {
        uint32_t ah[2][4];
#pragma unroll
        for (int mf = 0; mf < 2; mf++) {
            uint32_t coff = (((uint32_t)(ks * 2 + achunk)) << 4) ^ a_rx[mf];
            ldsm4(ah[mf], a_ad[mf] + coff);
        }
        uint32_t bh[4];
        {
            uint32_t coff = (((uint32_t)(ks * 2 + bchunk)) << 4) ^ b_rx;
            ldsm4(bh, b_ad + coff);
        }
#pragma unroll
        for (int mf = 0; mf < 2; mf++)
#pragma unroll
            for (int nf = 0; nf < 2; nf++) {
                int sel = nf * 2;
                mma16816(acc[mf][nf], ah[mf], bh[sel], bh[sel + 1]);
            }
    }
}

// store one P value into swizzled Pstage (single fp16 plane @PSTO)
__device__ __forceinline__ void sts_p(char* dsm, int row, int salcol, float val) {
    uint32_t off = (uint32_t)row * 256 + ((((uint32_t)(salcol >> 3)) ^ (uint32_t)(row & 7)) << 4)
                 + (uint32_t)((2 * salcol) & 15);
    *(__half*)(dsm + PSTO + off) = __float2half_rn(val);
}

// ---------------- K0a: decode indices, segment tables (parallel binary search) ----------------
__global__ void k_prep(const void* idx_raw, const void* cu_raw) {
    const int* i32 = (const int*)idx_raw;
    const int* c32 = (const int*)cu_raw;
    const bool idx64 = (i32[1] == 0);
    const bool cu64  = (c32[1] == 0);
    const int t = threadIdx.x;

    for (int i = t; i < NSALT; i += 256)
        g_idx[i] = idx64 ? (int)((const long long*)idx_raw)[i] : i32[i];
    if (t <= NSEG)
        g_cu[t] = cu64 ? (int)((const long long*)cu_raw)[t] : c32[t];
    for (int i = t; i < TT; i += 256) g_salpos[i] = -1;
    __syncthreads();
    for (int i = t; i < NSALT; i += 256) g_salpos[g_idx[i]] = i;
    if (t < NSEG) {
        // g_idx is sorted: binary search for segment bounds (replaces serial scan)
        int tgt = g_cu[t];
        int lo = 0, hi = NSALT;
        while (lo < hi) { int mid = (lo + hi) >> 1; if (g_idx[mid] < tgt) lo = mid + 1; else hi = mid; }
        int a = lo;
        tgt = g_cu[t + 1];
        lo = 0; hi = NSALT;
        while (lo < hi) { int mid = (lo + hi) >> 1; if (g_idx[mid] < tgt) lo = mid + 1; else hi = mid; }
        g_salst[t] = a;
        g_salcnt[t] = lo - a;
    }
}

// ---------------- K0b (merged): K cvt || build_vn || build_vd (single fp16) ----------------
__global__ void __launch_bounds__(256) k_pre(const float* __restrict__ kk,
                                             const float* __restrict__ v, const float* __restrict__ vc) {
    extern __shared__ float tile[];   // [32][129]
    const int bx = blockIdx.x;
    const int tid = threadIdx.x;

    if (bx < CVT_BLKS) {
        int i = bx * 256 + tid;
        float4 x = ((const float4*)kk)[i];
        __half2 h2[2];
        h2[0] = __floats2half2_rn(x.x, x.y);
        h2[1] = __floats2half2_rn(x.z, x.w);
        *(uint2*)(g_k + 4 * (size_t)i) = *(uint2*)h2;
        return;
    }

    if (bx < CVT_BLKS + VN_BLKS) {
        int t2 = bx - CVT_BLKS;
        int kc = t2 >> 3, g = t2 & 7;
#pragma unroll
        for (int it = 0; it < 4; it++) {
            int fi = tid + it * 256;
            int key = fi >> 5, c4 = fi & 31;
            int gk = kc * 32 + key;
            int sp = g_salpos[gk];
            const float* src = (sp >= 0) ? v + ((size_t)sp * NKV + g) * HD + c4 * 4
                                         : vc + ((size_t)gk * NKV + g) * HD + c4 * 4;
            float4 x = *(const float4*)src;
            float* tr = tile + key * 129 + c4 * 4;
            tr[0] = x.x; tr[1] = x.y; tr[2] = x.z; tr[3] = x.w;
        }
        __syncthreads();
#pragma unroll
        for (int it = 0; it < 8; it++) {
            int wi = tid + it * 256;
            int d = wi >> 4, kp = wi & 15;
            float v0 = tile[(2 * kp) * 129 + d], v1 = tile[(2 * kp + 1) * 129 + d];
            size_t dst = ((size_t)g * HD + d) * TT + kc * 32 + 2 * kp;
            *(__half2*)(g_vnT + dst) = __floats2half2_rn(v0, v1);
        }
        return;
    }

    {
        int t2 = bx - CVT_BLKS - VN_BLKS;
        int kc = t2 >> 3, g = t2 & 7;
#pragma unroll
        for (int it = 0; it < 4; it++) {
            int fi = tid + it * 256;
            int sidx = fi >> 5, c4 = fi & 31;
            int sal = kc * 32 + sidx;
            const float* pv = v  + ((size_t)sal * NKV + g) * HD + c4 * 4;
            const float* pc = vc + ((size_t)g_idx[sal] * NKV + g) * HD + c4 * 4;
            float4 a = *(const float4*)pv;
            float4 b = *(const float4*)pc;
            float* tr = tile + sidx * 129 + c4 * 4;
            tr[0] = a.x - b.x; tr[1] = a.y - b.y; tr[2] = a.z - b.z; tr[3] = a.w - b.w;
        }
        __syncthreads();
#pragma unroll
        for (int it = 0; it < 8; it++) {
            int wi = tid + it * 256;
            int d = wi >> 4, kp = wi & 15;
            float v0 = tile[(2 * kp) * 129 + d], v1 = tile[(2 * kp + 1) * 129 + d];
            size_t dst = ((size_t)g * HD + d) * NSALT + kc * 32 + 2 * kp;
            *(__half2*)(g_vdT + dst) = __floats2half2_rn(v0, v1);
        }
    }
}

// ---------------- K1: fused QK^T + exp + rowsum + delta-PV (64KB smem) ----------------
__device__ __forceinline__ void qk_loadK64(uint32_t sb, uint32_t buf, int tid, int nt, int s0, int L, int g) {
#pragma unroll
    for (int it = 0; it < 4; it++) {
        int idx = tid + it * 256;
        int r = idx >> 4, ch = idx & 15;
        uint32_t d = (uint32_t)(r * 256) + (((uint32_t)(ch ^ (r & 7))) << 4);
        int jg = nt * 64 + r;
        bool v = jg < L;
        size_t o = v ? (((size_t)(s0 + jg) * NKV + g) * HD + ch * 8) : 0;
        cpa16(sb + buf + d, g_k + o, v);
    }
}

__global__ void __launch_bounds__(256, 3) k_qk(const float* __restrict__ qf,
                                               const float* __restrict__ cc, float* __restrict__ outc,
                                               int sgOff) {
    extern __shared__ char dsm[];
    __shared__ int s_sp[SMAXK];
    __shared__ float s_red[64 * 4];
    const int sg = blockIdx.y + sgOff;
    const int s = sg >> 3, g = sg & 7;
    const int s0 = g_cu[s];
    const int L = g_cu[s + 1] - s0;
    const int mBase = blockIdx.x * 64;
    if (mBase >= 4 * L) return;
    const int salst = g_salst[s], salcnt = g_salcnt[s];

    const int tid = threadIdx.x, wid = tid >> 5, lane = tid & 31;
    const int wm = wid >> 2, wn = wid & 3;
    const uint32_t sb = smem_to_u32(dsm);

    qk_loadK64(sb, KB0, tid, 0, s0, L, g);
    CP_COMMIT();
    qk_loadK64(sb, KB1, tid, 1, s0, L, g);
    CP_COMMIT();

    for (int j = tid; j < L; j += 256) {
        int sp = g_salpos[s0 + j];
        s_sp[j] = sp >= 0 ? sp - salst : -1;
    }

    // zero Pstage (16KB)
    {
        uint4 z = make_uint4(0, 0, 0, 0);
#pragma unroll
        for (int it = 0; it < 4; it++)
            *(uint4*)(dsm + PSTO + (size_t)(tid + it * 256) * 16) = z;
    }

    // Q tile: fp32 -> fp16(q*SCALE_L2E) single plane, swizzled STS
#pragma unroll
    for (int it = 0; it < 4; it++) {
        int idx = tid + it * 256;
        int r = idx >> 4, ch = idx & 15;
        uint32_t d = (uint32_t)(r * 256) + (((uint32_t)(ch ^ (r & 7))) << 4);
        int mm = mBase + r, il = mm >> 2, hh = mm & 3;
        __half2 h2[4];
        if (il < L) {
            const float4* src = (const float4*)(qf + ((size_t)(s0 + il) * NH + 4 * g + hh) * HD + ch * 8);
            float4 x0 = src[0], x1 = src[1];
            h2[0] = __floats2half2_rn(x0.x * SCALE_L2E, x0.y * SCALE_L2E);
            h2[1] = __floats2half2_rn(x0.z * SCALE_L2E, x0.w * SCALE_L2E);
            h2[2] = __floats2half2_rn(x1.x * SCALE_L2E, x1.y * SCALE_L2E);
            h2[3] = __floats2half2_rn(x1.z * SCALE_L2E, x1.w * SCALE_L2E);
        } else {
            h2[0] = h2[1] = h2[2] = h2[3] = __floats2half2_rn(0.f, 0.f);
        }
        *(uint4*)(dsm + d) = *(uint4*)h2;
    }

    // per-row metadata (Posal base for salient rows)
    ll pb0[2], pb1[2];
    bool ok0[2], ok1[2];
    int rb[2];
#pragma unroll
    for (int mf = 0; mf < 2; mf++) {
        rb[mf] = wm * 32 + mf * 16 + (lane >> 2);
        int mr0 = mBase + rb[mf];
        int mr1 = mr0 + 8;
        int il0 = mr0 >> 2, h0 = mr0 & 3;
        int il1 = mr1 >> 2, h1 = mr1 & 3;
        ok0[mf] = il0 < L; ok1[mf] = il1 < L;
        int sp0 = ok0[mf] ? g_salpos[s0 + il0] : -1;
        int sp1 = ok1[mf] ? g_salpos[s0 + il1] : -1;
        pb0[mf] = sp0 >= 0 ? ((ll)sp0 * NH + 4 * g + h0) * SMAXK : -1;
        pb1[mf] = sp1 >= 0 ? ((ll)sp1 * NH + 4 * g + h1) * SMAXK : -1;
    }

    float rs0[2] = {0.f, 0.f}, rs1[2] = {0.f, 0.f};

    for (int nt = 0; nt < 8; nt++) {
        if (nt == 7) { CP_WAIT0(); } else { CP_WAIT1(); }
        __syncthreads();

        float acc[2][2][4];
#pragma unroll
        for (int a = 0; a < 2; a++)
#pragma unroll
            for (int b = 0; b < 2; b++)
#pragma unroll
                for (int c = 0; c < 4; c++) acc[a][b][c] = 0.f;

        uint32_t buf = (nt & 1) ? KB1 : KB0;
        hmma_n64(sb, QOFF, buf, acc, wid, lane);
        __syncthreads();
        if (nt < 6) {
            qk_loadK64(sb, buf, tid, nt + 2, s0, L, g);
            CP_COMMIT();
        }

        // epilogue: exp (scale pre-folded), rowsum, Pstage STS, Posal STG
#pragma unroll
        for (int nf = 0; nf < 2; nf++) {
            int col = nt * 64 + wn * 16 + nf * 8 + (lane & 3) * 2;
            bool c0 = col < L, c1 = col + 1 < L;
            int spa = c0 ? s_sp[col] : -1;
            int spb = c1 ? s_sp[col + 1] : -1;
#pragma unroll
            for (int mf = 0; mf < 2; mf++) {
                float* c = acc[mf][nf];
                float e0 = (ok0[mf] && c0) ? fexp2(c[0]) : 0.f;
                float e1 = (ok0[mf] && c1) ? fexp2(c[1]) : 0.f;
                float e2 = (ok1[mf] && c0) ? fexp2(c[2]) : 0.f;
                float e3 = (ok1[mf] && c1) ? fexp2(c[3]) : 0.f;
                rs0[mf] += e0 + e1;
                rs1[mf] += e2 + e3;
                int r0 = rb[mf], r1 = r0 + 8;
                if (spa >= 0) {
                    if (ok0[mf]) sts_p(dsm, r0, spa, e0);
                    if (ok1[mf]) sts_p(dsm, r1, spa, e2);
                }
                if (spb >= 0) {
                    if (ok0[mf]) sts_p(dsm, r0, spb, e1);
                    if (ok1[mf]) sts_p(dsm, r1, spb, e3);
                }
                if (pb0[mf] >= 0 && c0)
                    *(__half2*)(g_Posal + pb0[mf] + col) = __floats2half2_rn(e0, e1);
                if (pb1[mf] >= 0 && c0)
                    *(__half2*)(g_Posal + pb1[mf] + col) = __floats2half2_rn(e2, e3);
            }
        }
    }

    // vdT (32KB) -> [16K,48K): both K buffers now free
#pragma unroll
    for (int it = 0; it < 8; it++) {
        int idx = tid + it * 256;
        int r = idx >> 4, ch = idx & 15;
        uint32_t d = (uint32_t)(r * 256) + (((uint32_t)(ch ^ (r & 7))) << 4);
        bool vb = (ch * 8 < salcnt);
        size_t ib = vb ? (((size_t)(g * HD + r)) * NSALT + salst + ch * 8) : 0;
        cpa16(sb + KB0 + d, g_vdT + ib, vb);
    }
    CP_COMMIT();

    // rowsum reduction across n-warps (overlaps vdT load)
#pragma unroll
    for (int mf = 0; mf < 2; mf++) {
        rs0[mf] += __shfl_xor_sync(0xffffffffu, rs0[mf], 1);
        rs0[mf] += __shfl_xor_sync(0xffffffffu, rs0[mf], 2);
        rs1[mf] += __shfl_xor_sync(0xffffffffu, rs1[mf], 1);
        rs1[mf] += __shfl_xor_sync(0xffffffffu, rs1[mf], 2);
    }
    if ((lane & 3) == 0) {
#pragma unroll
        for (int mf = 0; mf < 2; mf++) {
            s_red[rb[mf] * 4 + wn] = rs0[mf];
            s_red[(rb[mf] + 8) * 4 + wn] = rs1[mf];
        }
    }
    CP_WAIT0();
    __syncthreads();

    // g_inv for osal
    if (tid < 64) {
        int mm = mBase + tid, il = mm >> 2, h = mm & 3;
        if (il < L) {
            float s4 = s_red[tid * 4] + s_red[tid * 4 + 1] + s_red[tid * 4 + 2] + s_red[tid * 4 + 3];
            g_inv[(size_t)(s0 + il) * NH + 4 * g + h] = 1.f / s4;
        }
    }

    // per-row inv + write mask (salient rows overwritten by k_pv)
    float inv0[2], inv1[2];
    bool w0[2], w1[2];
    size_t id0[2], id1[2];
#pragma unroll
    for (int mf = 0; mf < 2; mf++) {
        int r0 = rb[mf], r1 = r0 + 8;
        int mr0 = mBase + r0, mr1 = mBase + r1;
        int il0 = mr0 >> 2, h0 = mr0 & 3;
        int il1 = mr1 >> 2, h1 = mr1 & 3;
        w0[mf] = (il0 < L) && (pb0[mf] < 0);
        w1[mf] = (il1 < L) && (pb1[mf] < 0);
        inv0[mf] = w0[mf] ? 1.f / (s_red[r0 * 4] + s_red[r0 * 4 + 1] + s_red[r0 * 4 + 2] + s_red[r0 * 4 + 3]) : 0.f;
        inv1[mf] = w1[mf] ? 1.f / (s_red[r1 * 4] + s_red[r1 * 4 + 1] + s_red[r1 * 4 + 2] + s_red[r1 * 4 + 3]) : 0.f;
        id0[mf] = (size_t)(s0 + il0) * NH + 4 * g + h0;
        id1[mf] = (size_t)(s0 + il1) * NH + 4 * g + h1;
    }

    // delta PV in two N=64 halves (register-light)
#pragma unroll
    for (int ph = 0; ph < 2; ph++) {
        float pv[2][2][4];
#pragma unroll
        for (int a = 0; a < 2; a++)
#pragma unroll
            for (int b = 0; b < 2; b++)
#pragma unroll
                for (int c = 0; c < 4; c++) pv[a][b][c] = 0.f;
        hmma_n64(sb, PSTO, KB0 + (uint32_t)ph * 16384u, pv, wid, lane);

#pragma unroll
        for (int mf = 0; mf < 2; mf++) {
#pragma unroll
            for (int nf = 0; nf < 2; nf++) {
                int dcol = ph * 64 + wn * 16 + nf * 8 + (lane & 3) * 2;
                float* c = pv[mf][nf];
                if (w0[mf]) {
                    size_t ob = id0[mf] * HD + dcol;
                    float2 cv = *(const float2*)(cc + ob);
                    *(float2*)(outc + ob) = make_float2(cv.x + inv0[mf] * c[0], cv.y + inv0[mf] * c[1]);
                }
                if (w1[mf]) {
                    size_t ob = id1[mf] * HD + dcol;
                    float2 cv = *(const float2*)(cc + ob);
                    *(float2*)(outc + ob) = make_float2(cv.x + inv1[mf] * c[2], cv.y + inv1[mf] * c[3]);
                }
            }
        }
    }
}

// ---------------- K2: osal: salient rows out = inv * (Posal @ vnT) ----------------
__global__ void __launch_bounds__(256, 2) k_pv(float* __restrict__ outc) {
    extern __shared__ char dsm[];
    const int sg = blockIdx.y;
    const int s = sg >> 3, g = sg & 7;
    const int s0 = g_cu[s];
    const int L = g_cu[s + 1] - s0;
    const int salst = g_salst[s], salcnt = g_salcnt[s];

    const int tid = threadIdx.x, wid = tid >> 5, lane = tid & 31;
    const int wm = wid >> 2, wn = wid & 3;
    const uint32_t sb = smem_to_u32(dsm);

    const int mBase = blockIdx.x * 64;
    if (mBase >= 4 * salcnt) return;

    auto loadA = [&](uint32_t buf, int kc) {
#pragma unroll
        for (int it = 0; it < 4; it++) {
            int idx = tid + it * 256;
            int r = idx >> 4, ch = idx & 15;
            uint32_t d = (uint32_t)(r * 256) + (((uint32_t)(ch ^ (r & 7))) << 4);
            int m = mBase + r, saloc = m >> 2, hh = m & 3;
            int kk = kc * 128 + ch * 8;
            bool va = (saloc < salcnt) && (kk < L);
            size_t ia = va ? (((size_t)(salst + saloc) * NH + 4 * g + hh) * SMAXK + kk) : 0;
            cpa16(sb + buf + d, g_Posal + ia, va);
        }
    };
    auto loadB = [&](uint32_t buf, int kc) {
#pragma unroll
        for (int it = 0; it < 8; it++) {
            int idx = tid + it * 256;
            int r = idx >> 4, ch = idx & 15;
            uint32_t d = (uint32_t)(r * 256) + (((uint32_t)(ch ^ (r & 7))) << 4);
            int kk = kc * 128 + ch * 8;
            bool vb = (kk < L);
            size_t ib = vb ? (((size_t)(g * HD + r)) * TT + s0 + kk) : 0;
            cpa16(sb + buf + d, g_vnT + ib, vb);
        }
    };

    const int nkc = (L + 127) / 128;
    loadA(PV_A0, 0); loadB(PV_B0, 0);
    CP_COMMIT();
    if (nkc > 1) { loadA(PV_A1, 1); loadB(PV_B1, 1); }
    CP_COMMIT();

    float acc[2][4][4];
#pragma unroll
    for (int a = 0; a < 2; a++)
#pragma unroll
        for (int b = 0; b < 4; b++)
#pragma unroll
            for (int c = 0; c < 4; c++) acc[a][b][c] = 0.f;

    for (int kc = 0; kc < nkc; kc++) {
        if (kc == nkc - 1) { CP_WAIT0(); } else { CP_WAIT1(); }
        __syncthreads();
        uint32_t aB = (kc & 1) ? PV_A1 : PV_A0;
        uint32_t bB = (kc & 1) ? PV_B1 : PV_B0;
        hmma_1p(sb, aB, bB, acc, wid, lane);
        __syncthreads();
        if (kc + 2 < nkc) {
            loadA(aB, kc + 2); loadB(bB, kc + 2);
            CP_COMMIT();
        }
    }

#pragma unroll
    for (int mf = 0; mf < 2; mf++) {
        int mr0 = mBase + wm * 32 + mf * 16 + (lane >> 2);
        int mr1 = mr0 + 8;
        int sa0 = mr0 >> 2, h0 = mr0 & 3;
        int sa1 = mr1 >> 2, h1 = mr1 & 3;
        bool ok0 = sa0 < salcnt, ok1 = sa1 < salcnt;
        size_t id0 = 0, id1 = 0;
        float inv0 = 0.f, inv1 = 0.f;
        if (ok0) { id0 = (size_t)g_idx[salst + sa0] * NH + 4 * g + h0; inv0 = g_inv[id0]; }
        if (ok1) { id1 = (size_t)g_idx[salst + sa1] * NH + 4 * g + h1; inv1 = g_inv[id1]; }
#pragma unroll
        for (int nf = 0; nf < 4; nf++) {
            int dcol = wn * 32 + nf * 8 + (lane & 3) * 2;
            float* c = acc[mf][nf];
            if (ok0) *(float2*)(outc + id0 * HD + dcol) = make_float2(inv0 * c[0], inv0 * c[1]);
            if (ok1) *(float2*)(outc + id1 * HD + dcol) = make_float2(inv1 * c[2], inv1 * c[3]);
        }
    }
}

// ---------------- K3: per-row cosine similarity (warp-shuffle reduction) ----------------
__global__ void __launch_bounds__(512) k_cos(const float* __restrict__ cc, const float* __restrict__ outc,
                                             float* __restrict__ cosv) {
    const int tid = threadIdx.x, wid = tid >> 5, lane = tid & 31;
    size_t base = (size_t)blockIdx.x * (NH * HD);
    const float4* a4 = (const float4*)(cc + base);
    const float4* b4 = (const float4*)(outc + base);
    float ab = 0.f, aa = 0.f, bb = 0.f;
#pragma unroll
    for (int j = 0; j < 2; j++) {
        float4 x = a4[tid + j * 512], y = b4[tid + j * 512];
        ab += x.x * y.x + x.y * y.y + x.z * y.z + x.w * y.w;
        aa += x.x * x.x + x.y * x.y + x.z * x.z + x.w * x.w;
        bb += y.x * y.x + y.y * y.y + y.z * y.z + y.w * y.w;
    }
#pragma unroll
    for (int o = 16; o; o >>= 1) {
        ab += __shfl_xor_sync(0xffffffffu, ab, o);
        aa += __shfl_xor_sync(0xffffffffu, aa, o);
        bb += __shfl_xor_sync(0xffffffffu, bb, o);
    }
    __shared__ float sh[3][16];
    if (lane == 0) { sh[0][wid] = ab; sh[1][wid] = aa; sh[2][wid] = bb; }
    __syncthreads();
    if (tid < 32) {
        float a2 = (tid < 16) ? sh[0][tid] : 0.f;
        float b2 = (tid < 16) ? sh[1][tid] : 0.f;
        float c2 = (tid < 16) ? sh[2][tid] : 0.f;
#pragma unroll
        for (int o = 8; o; o >>= 1) {
            a2 += __shfl_xor_sync(0xffffffffu, a2, o);
            b2 += __shfl_xor_sync(0xffffffffu, b2, o);
            c2 += __shfl_xor_sync(0xffffffffu, c2, o);
        }
        if (tid == 0)
            cosv[blockIdx.x] = a2 / (sqrtf(b2) * sqrtf(c2) + 1e-8f);
    }
}

// ---------------- launch ----------------
extern "C" void kernel_launch(void* const* d_in, const int* in_sizes, int n_in,
                              void* d_out, int out_size) {
    const float* q       = (const float*)d_in[0];
    const float* k       = (const float*)d_in[1];
    const float* v       = (const float*)d_in[2];
    const float* v_cache = (const float*)d_in[3];
    const float* c_cache = (const float*)d_in[4];
    const void*  idx     = d_in[5];
    const void*  cu      = d_in[6];

    float* outc = (float*)d_out;
    float* cosv = outc + (size_t)(out_size - TT);

    cudaFuncSetAttribute(k_qk,  cudaFuncAttributeMaxDynamicSharedMemorySize, 65536);
    cudaFuncSetAttribute(k_pv,  cudaFuncAttributeMaxDynamicSharedMemorySize, 98304);
    cudaFuncSetAttribute(k_pre, cudaFuncAttributeMaxDynamicSharedMemorySize, 16512);

    k_prep<<<1, 256>>>(idx, cu);
    k_pre<<<CVT_BLKS + VN_BLKS + VD_BLKS, 256, 16512>>>(k, v, v_cache);
    // k_qk split into two half-grids (independent sg groups; also shifts the
    // ncu capture window onto a k_qk instance for evidence)
    k_qk<<<dim3(32, 16), 256, 65536>>>(q, c_cache, outc, 0);
    k_qk<<<dim3(32, 16), 256, 65536>>>(q, c_cache, outc, 16);
    k_pv<<<dim3(8, 32), 256, 98304>>>(outc);
    k_cos<<<TT, 512>>>(c_cache, outc, cosv);
}